// round 4
// baseline (speedup 1.0000x reference)
#include <cuda_runtime.h>
#include <cuda_bf16.h>

// Problem constants
#define NN 50000
#define EE 800000
#define K_CHEB 16
#define BN_EPS 1e-5f

// ---------------- scratch (device globals; no allocation allowed) ----------------
__device__ int   g_is64;            // 1 if edge_index stored as int64, 0 if int32
__device__ int   g_deg[NN];
__device__ float g_dinv[NN];
__device__ int   g_cnt[NN];
__device__ int   g_rowptr[NN + 1];
__device__ int   g_fill[NN];
__device__ int   g_col[EE];
__device__ float g_w[EE];
__device__ int   g_bsum[64];
__device__ int   g_total[1];

__device__ float g_TxA[(size_t)NN * 128];
__device__ float g_TxB[(size_t)NN * 128];
__device__ float g_TxC[(size_t)NN * 128];
__device__ float g_out1[(size_t)NN * 128];
__device__ float g_h[(size_t)NN * 128];
__device__ float g_out2[(size_t)NN * 32];
__device__ float g_stats[2 * 128];

// Device-side buffer resolution (no host-side symbol addressing needed).
__device__ __forceinline__ float* gbuf(int i) {
    switch (i) {
        case 0: return g_TxA;
        case 1: return g_TxB;
        case 2: return g_TxC;
        case 3: return g_out1;
        case 4: return g_h;
        default: return g_out2;
    }
}

// ---------------- edge dtype detection ----------------
// If edge_index is int64, the high 32-bit word of every value is 0 (values in
// [0, 50000)). If int32, the "high words" are actually other random indices —
// the chance that 4096 of them are all zero is nil.

__global__ void detect_init_k() {
    if (threadIdx.x == 0) g_is64 = 1;
}

__global__ void detect_k(const int* __restrict__ ei32) {
    int e = blockIdx.x * blockDim.x + threadIdx.x;
    if (e >= 4096) return;
    if (ei32[2 * e + 1] != 0) g_is64 = 0;
}

__device__ __forceinline__ void load_edge(const int* __restrict__ ei32, int e,
                                          int& s, int& d) {
    if (g_is64) {
        s = ei32[2 * e];
        d = ei32[2 * (EE + e)];
    } else {
        s = ei32[e];
        d = ei32[EE + e];
    }
}

// ---------------- zero-init kernels ----------------

__global__ void zero_graph_k() {
    int i = blockIdx.x * blockDim.x + threadIdx.x;
    if (i < NN) { g_deg[i] = 0; g_cnt[i] = 0; }
}

__global__ void zero_stats_k() {
    int i = threadIdx.x;
    if (i < 2 * 128) g_stats[i] = 0.f;
}

// ---------------- graph preprocessing ----------------

__global__ void deg_count_k(const int* __restrict__ ei32) {
    int e = blockIdx.x * blockDim.x + threadIdx.x;
    if (e >= EE) return;
    int s, d;
    load_edge(ei32, e, s, d);
    if ((unsigned)s >= NN || (unsigned)d >= NN) return;  // safety: never crash
    if (s != d) {
        atomicAdd(&g_deg[s], 1);
        atomicAdd(&g_cnt[d], 1);
    }
}

__global__ void dinv_k() {
    int i = blockIdx.x * blockDim.x + threadIdx.x;
    if (i >= NN) return;
    int d = g_deg[i];
    g_dinv[i] = (d > 0) ? rsqrtf((float)d) : 0.0f;
}

// exclusive scan of g_cnt into g_rowptr (3-phase)
__global__ void scan_block_k() {
    __shared__ int sh[1024];
    int i = blockIdx.x * 1024 + threadIdx.x;
    int v = (i < NN) ? g_cnt[i] : 0;
    sh[threadIdx.x] = v;
    __syncthreads();
    for (int off = 1; off < 1024; off <<= 1) {
        int t = (threadIdx.x >= off) ? sh[threadIdx.x - off] : 0;
        __syncthreads();
        sh[threadIdx.x] += t;
        __syncthreads();
    }
    if (i < NN) g_rowptr[i] = sh[threadIdx.x] - v;  // exclusive, block-local
    if (threadIdx.x == 1023) g_bsum[blockIdx.x] = sh[1023];
}

__global__ void scan_top_k(int nb) {
    if (threadIdx.x == 0) {
        int run = 0;
        for (int b = 0; b < nb; b++) { int t = g_bsum[b]; g_bsum[b] = run; run += t; }
        g_total[0] = run;
    }
}

__global__ void scan_add_k() {
    int i = blockIdx.x * blockDim.x + threadIdx.x;
    if (i < NN) {
        int v = g_rowptr[i] + g_bsum[i >> 10];
        g_rowptr[i] = v;
        g_fill[i] = v;
    }
    if (i == NN) g_rowptr[NN] = g_total[0];
}

__global__ void scatter_k(const int* __restrict__ ei32) {
    int e = blockIdx.x * blockDim.x + threadIdx.x;
    if (e >= EE) return;
    int s, d;
    load_edge(ei32, e, s, d);
    if ((unsigned)s >= NN || (unsigned)d >= NN) return;
    if (s == d) return;
    int pos = atomicAdd(&g_fill[d], 1);
    g_col[pos] = s;
    g_w[pos] = -g_dinv[s] * g_dinv[d];
}

// ---------------- sparse propagation (F = 128, warp per dst row) ----------------

__global__ void prop_first_k(const float* __restrict__ xext, int x_idx, int y_idx) {
    const float* __restrict__ X = (x_idx < 0) ? xext : gbuf(x_idx);
    float* __restrict__ Y = gbuf(y_idx);
    int wid = (blockIdx.x * blockDim.x + threadIdx.x) >> 5;
    int lane = threadIdx.x & 31;
    if (wid >= NN) return;
    int beg = g_rowptr[wid], end = g_rowptr[wid + 1];
    float4 acc = make_float4(0.f, 0.f, 0.f, 0.f);
#pragma unroll 4
    for (int e = beg; e < end; e++) {
        int s = g_col[e];
        float w = g_w[e];
        float4 v = ((const float4*)(X + (size_t)s * 128))[lane];
        acc.x = fmaf(w, v.x, acc.x);
        acc.y = fmaf(w, v.y, acc.y);
        acc.z = fmaf(w, v.z, acc.z);
        acc.w = fmaf(w, v.w, acc.w);
    }
    ((float4*)(Y + (size_t)wid * 128))[lane] = acc;
}

__global__ void prop_rec_k(const float* __restrict__ xext,
                           int x1_idx, int x0_idx, int y_idx) {
    const float* __restrict__ X1 = (x1_idx < 0) ? xext : gbuf(x1_idx);
    const float* __restrict__ X0 = (x0_idx < 0) ? xext : gbuf(x0_idx);
    float* __restrict__ Y = gbuf(y_idx);
    int wid = (blockIdx.x * blockDim.x + threadIdx.x) >> 5;
    int lane = threadIdx.x & 31;
    if (wid >= NN) return;
    int beg = g_rowptr[wid], end = g_rowptr[wid + 1];
    float4 acc = make_float4(0.f, 0.f, 0.f, 0.f);
#pragma unroll 4
    for (int e = beg; e < end; e++) {
        int s = g_col[e];
        float w = g_w[e];
        float4 v = ((const float4*)(X1 + (size_t)s * 128))[lane];
        acc.x = fmaf(w, v.x, acc.x);
        acc.y = fmaf(w, v.y, acc.y);
        acc.z = fmaf(w, v.z, acc.z);
        acc.w = fmaf(w, v.w, acc.w);
    }
    float4 p = ((const float4*)(X0 + (size_t)wid * 128))[lane];
    float4 o;
    o.x = 2.f * acc.x - p.x;
    o.y = 2.f * acc.y - p.y;
    o.z = 2.f * acc.z - p.z;
    o.w = 2.f * acc.w - p.w;
    ((float4*)(Y + (size_t)wid * 128))[lane] = o;
}

// ---------------- GEMMs: C[n x FO] = (ACC ? C : 0) + A[n x 128] * B[128 x FO] ----

// FO = 128: 64x128 tile, 128 threads, 8x8 per-thread register tile
template <int ACC>
__global__ void gemm128_k(const float* __restrict__ Aext, int a_idx,
                          const float* __restrict__ B, int c_idx, int n) {
    const float* __restrict__ A = (a_idx < 0) ? Aext : gbuf(a_idx);
    float* __restrict__ C = gbuf(c_idx);
    const int m0 = blockIdx.x * 64;
    __shared__ float As[16][65];
    __shared__ float Bs[16][128];
    const int tid = threadIdx.x;
    const int ty = tid >> 4;   // 0..7
    const int tx = tid & 15;   // 0..15
    float acc[8][8];
#pragma unroll
    for (int r = 0; r < 8; r++)
#pragma unroll
        for (int c = 0; c < 8; c++) acc[r][c] = 0.f;

    for (int kk = 0; kk < 128; kk += 16) {
#pragma unroll
        for (int i = tid; i < 64 * 16; i += 128) {
            int m = i >> 4, t = i & 15;
            int row = m0 + m;
            As[t][m] = (row < n) ? A[(size_t)row * 128 + kk + t] : 0.f;
        }
#pragma unroll
        for (int i = tid; i < 16 * 128; i += 128) {
            int t = i >> 7, c = i & 127;
            Bs[t][c] = B[(size_t)(kk + t) * 128 + c];
        }
        __syncthreads();
#pragma unroll
        for (int t = 0; t < 16; t++) {
            float a[8], b[8];
#pragma unroll
            for (int r = 0; r < 8; r++) a[r] = As[t][ty * 8 + r];
#pragma unroll
            for (int c = 0; c < 8; c++) b[c] = Bs[t][tx * 8 + c];
#pragma unroll
            for (int r = 0; r < 8; r++)
#pragma unroll
                for (int c = 0; c < 8; c++)
                    acc[r][c] = fmaf(a[r], b[c], acc[r][c]);
        }
        __syncthreads();
    }
#pragma unroll
    for (int r = 0; r < 8; r++) {
        int row = m0 + ty * 8 + r;
        if (row < n) {
#pragma unroll
            for (int c = 0; c < 8; c += 4) {
                float4* p = (float4*)&C[(size_t)row * 128 + tx * 8 + c];
                float4 v;
                if (ACC) {
                    v = *p;
                    v.x += acc[r][c + 0];
                    v.y += acc[r][c + 1];
                    v.z += acc[r][c + 2];
                    v.w += acc[r][c + 3];
                } else {
                    v.x = acc[r][c + 0];
                    v.y = acc[r][c + 1];
                    v.z = acc[r][c + 2];
                    v.w = acc[r][c + 3];
                }
                *p = v;
            }
        }
    }
}

// FO = 32: 128x32 tile, 128 threads, 8x4 per-thread register tile
template <int ACC>
__global__ void gemm32_k(const float* __restrict__ Aext, int a_idx,
                         const float* __restrict__ B, int c_idx, int n) {
    const float* __restrict__ A = (a_idx < 0) ? Aext : gbuf(a_idx);
    float* __restrict__ C = gbuf(c_idx);
    const int m0 = blockIdx.x * 128;
    __shared__ float As[16][129];
    __shared__ float Bs[16][33];
    const int tid = threadIdx.x;
    const int ty = tid >> 3;  // 0..15
    const int tx = tid & 7;   // 0..7
    float acc[8][4];
#pragma unroll
    for (int r = 0; r < 8; r++)
#pragma unroll
        for (int c = 0; c < 4; c++) acc[r][c] = 0.f;

    for (int kk = 0; kk < 128; kk += 16) {
#pragma unroll
        for (int i = tid; i < 128 * 16; i += 128) {
            int m = i >> 4, t = i & 15;
            int row = m0 + m;
            As[t][m] = (row < n) ? A[(size_t)row * 128 + kk + t] : 0.f;
        }
#pragma unroll
        for (int i = tid; i < 16 * 32; i += 128) {
            int t = i >> 5, c = i & 31;
            Bs[t][c] = B[(size_t)(kk + t) * 32 + c];
        }
        __syncthreads();
#pragma unroll
        for (int t = 0; t < 16; t++) {
            float a[8], b[4];
#pragma unroll
            for (int r = 0; r < 8; r++) a[r] = As[t][ty * 8 + r];
#pragma unroll
            for (int c = 0; c < 4; c++) b[c] = Bs[t][tx * 4 + c];
#pragma unroll
            for (int r = 0; r < 8; r++)
#pragma unroll
                for (int c = 0; c < 4; c++)
                    acc[r][c] = fmaf(a[r], b[c], acc[r][c]);
        }
        __syncthreads();
    }
#pragma unroll
    for (int r = 0; r < 8; r++) {
        int row = m0 + ty * 8 + r;
        if (row < n) {
            float4* p = (float4*)&C[(size_t)row * 32 + tx * 4];
            float4 v;
            if (ACC) {
                v = *p;
                v.x += acc[r][0];
                v.y += acc[r][1];
                v.z += acc[r][2];
                v.w += acc[r][3];
            } else {
                v.x = acc[r][0];
                v.y = acc[r][1];
                v.z = acc[r][2];
                v.w = acc[r][3];
            }
            *p = v;
        }
    }
}

// ---------------- BatchNorm (training-mode) + ReLU ----------------

__global__ void bn_stats_k(int v_idx, int total, int F) {
    const float* __restrict__ V = gbuf(v_idx);
    int idx = blockIdx.x * blockDim.x + threadIdx.x;
    int stride = gridDim.x * blockDim.x;  // multiple of F by construction
    float s = 0.f, s2 = 0.f;
    int col = idx % F;
    for (int i = idx; i < total; i += stride) {
        float v = V[i];
        s += v;
        s2 = fmaf(v, v, s2);
    }
    atomicAdd(&g_stats[col], s);
    atomicAdd(&g_stats[F + col], s2);
}

__global__ void bn_finalize_k(const float* __restrict__ gamma,
                              const float* __restrict__ beta, int F, float invN) {
    int c = threadIdx.x;
    if (c < F) {
        float mu = g_stats[c] * invN;
        float var = g_stats[F + c] * invN - mu * mu;
        float sc = gamma[c] * rsqrtf(var + BN_EPS);
        g_stats[c] = sc;                      // scale
        g_stats[F + c] = beta[c] - sc * mu;   // shift
    }
}

__global__ void bn_apply_k(int v_idx, float* __restrict__ Yext, int y_idx,
                           int total, int F) {
    const float* __restrict__ V = gbuf(v_idx);
    float* __restrict__ Y = (y_idx < 0) ? Yext : gbuf(y_idx);
    int idx = blockIdx.x * blockDim.x + threadIdx.x;
    if (idx >= total) return;
    int c = idx % F;
    float y = fmaf(g_stats[c], V[idx], g_stats[F + c]);
    Y[idx] = fmaxf(y, 0.f);
}

// ---------------- host launch: kernel launches ONLY ----------------

extern "C" void kernel_launch(void* const* d_in, const int* in_sizes, int n_in,
                              void* d_out, int out_size) {
    const float* x  = (const float*)d_in[0];
    const int* ei32 = (const int*)d_in[1];   // dtype detected on device
    const float* W1 = (const float*)d_in[2];
    const float* W2 = (const float*)d_in[4];
    const float* g1 = (const float*)d_in[6];
    const float* be1 = (const float*)d_in[7];
    const float* g2 = (const float*)d_in[8];
    const float* be2 = (const float*)d_in[9];
    float* out = (float*)d_out;

    // Buffer indices: 0=TxA 1=TxB 2=TxC 3=out1 4=h 5=out2, -1 = external ptr arg
    const int BA = 0, BB = 1, BC = 2, BO1 = 3, BH = 4, BO2 = 5, EXT = -1;

    // --- edge dtype detection + graph preprocessing -> CSR with weights ---
    detect_init_k<<<1, 32>>>();
    detect_k<<<16, 256>>>(ei32);
    zero_graph_k<<<(NN + 255) / 256, 256>>>();
    deg_count_k<<<(EE + 255) / 256, 256>>>(ei32);
    dinv_k<<<(NN + 255) / 256, 256>>>();
    int nb = (NN + 1023) / 1024;
    scan_block_k<<<nb, 1024>>>();
    scan_top_k<<<1, 32>>>(nb);
    scan_add_k<<<(NN + 1 + 255) / 256, 256>>>();
    scatter_k<<<(EE + 255) / 256, 256>>>(ei32);

    const int PROP_GRID = (NN * 32 + 255) / 256;
    const int G128 = (NN + 63) / 64;
    const int G32 = (NN + 127) / 128;

    // --- layer 1: ChebConv(128 -> 128) ---
    gemm128_k<0><<<G128, 128>>>(x, EXT, W1, BO1, NN);
    prop_first_k<<<PROP_GRID, 256>>>(x, EXT, BA);
    gemm128_k<1><<<G128, 128>>>(nullptr, BA, W1 + 1 * 128 * 128, BO1, NN);
    {
        int pp = EXT;  // external x at k=2
        int p1 = BA;
        const int bufs[3] = {BA, BB, BC};
        int bi = 1;
        for (int k = 2; k < K_CHEB; k++) {
            int dst = bufs[bi];
            bi = (bi + 1) % 3;
            prop_rec_k<<<PROP_GRID, 256>>>(x, p1, pp, dst);
            gemm128_k<1><<<G128, 128>>>(nullptr, dst, W1 + (size_t)k * 128 * 128, BO1, NN);
            pp = p1;
            p1 = dst;
        }
    }
    // BN + ReLU (bias cancels in BN mean subtraction)
    zero_stats_k<<<1, 256>>>();
    bn_stats_k<<<256, 256>>>(BO1, NN * 128, 128);
    bn_finalize_k<<<1, 128>>>(g1, be1, 128, 1.0f / NN);
    bn_apply_k<<<(NN * 128 + 255) / 256, 256>>>(BO1, nullptr, BH, NN * 128, 128);

    // --- layer 2: ChebConv(128 -> 32) ---
    gemm32_k<0><<<G32, 128>>>(nullptr, BH, W2, BO2, NN);
    prop_first_k<<<PROP_GRID, 256>>>(nullptr, BH, BA);
    gemm32_k<1><<<G32, 128>>>(nullptr, BA, W2 + 1 * 128 * 32, BO2, NN);
    {
        int pp = BH;
        int p1 = BA;
        const int bufs[3] = {BA, BB, BC};
        int bi = 1;
        for (int k = 2; k < K_CHEB; k++) {
            int dst = bufs[bi];
            bi = (bi + 1) % 3;
            prop_rec_k<<<PROP_GRID, 256>>>(nullptr, p1, pp, dst);
            gemm32_k<1><<<G32, 128>>>(nullptr, dst, W2 + (size_t)k * 128 * 32, BO2, NN);
            pp = p1;
            p1 = dst;
        }
    }
    zero_stats_k<<<1, 256>>>();
    bn_stats_k<<<256, 256>>>(BO2, NN * 32, 32);
    bn_finalize_k<<<1, 32>>>(g2, be2, 32, 1.0f / NN);
    bn_apply_k<<<(NN * 32 + 255) / 256, 256>>>(BO2, out, EXT, NN * 32, 32);
}

// round 5
// speedup vs baseline: 1.0923x; 1.0923x over previous
#include <cuda_runtime.h>
#include <cuda_fp16.h>

// Problem constants
#define NN 50000
#define EE 800000
#define K_CHEB 16
#define BN_EPS 1e-5f

// ---------------- scratch (device globals; no allocation allowed) ----------------
__device__ int   g_is64;            // 1 if edge_index stored as int64, 0 if int32
__device__ int   g_deg[NN];
__device__ float g_dinv[NN];
__device__ int   g_cnt[NN];
__device__ int   g_rowptr[NN + 1];
__device__ int   g_fill[NN];
__device__ int   g_col[EE];
__device__ float g_w[EE];
__device__ int   g_bsum[64];
__device__ int   g_total[1];

// fp16 Chebyshev buffers (gather sources) + fp32 accumulation buffers
__device__ __half g_TxA[(size_t)NN * 128];
__device__ __half g_TxB[(size_t)NN * 128];
__device__ __half g_TxC[(size_t)NN * 128];
__device__ __half g_xh[(size_t)NN * 128];
__device__ __half g_hh[(size_t)NN * 128];
__device__ float  g_out1[(size_t)NN * 128];
__device__ float  g_h[(size_t)NN * 128];
__device__ float  g_out2[(size_t)NN * 32];
__device__ float  g_stats[2 * 128];

// Device-side buffer resolution (no host-side symbol addressing allowed).
// half buffers: 0=TxA 1=TxB 2=TxC 3=xh 4=hh
__device__ __forceinline__ __half* hbuf(int i) {
    switch (i) {
        case 0: return g_TxA;
        case 1: return g_TxB;
        case 2: return g_TxC;
        case 3: return g_xh;
        default: return g_hh;
    }
}
// float buffers: 0=out1 1=h 2=out2
__device__ __forceinline__ float* fbuf(int i) {
    switch (i) {
        case 0: return g_out1;
        case 1: return g_h;
        default: return g_out2;
    }
}

// ---------------- edge dtype detection ----------------

__global__ void detect_init_k() {
    if (threadIdx.x == 0) g_is64 = 1;
}

__global__ void detect_k(const int* __restrict__ ei32) {
    int e = blockIdx.x * blockDim.x + threadIdx.x;
    if (e >= 4096) return;
    if (ei32[2 * e + 1] != 0) g_is64 = 0;
}

__device__ __forceinline__ void load_edge(const int* __restrict__ ei32, int e,
                                          int& s, int& d) {
    if (g_is64) {
        s = ei32[2 * e];
        d = ei32[2 * (EE + e)];
    } else {
        s = ei32[e];
        d = ei32[EE + e];
    }
}

// ---------------- zero-init kernels ----------------

__global__ void zero_graph_k() {
    int i = blockIdx.x * blockDim.x + threadIdx.x;
    if (i < NN) { g_deg[i] = 0; g_cnt[i] = 0; }
}

__global__ void zero_stats_k() {
    int i = threadIdx.x;
    if (i < 2 * 128) g_stats[i] = 0.f;
}

// ---------------- graph preprocessing ----------------

__global__ void deg_count_k(const int* __restrict__ ei32) {
    int e = blockIdx.x * blockDim.x + threadIdx.x;
    if (e >= EE) return;
    int s, d;
    load_edge(ei32, e, s, d);
    if ((unsigned)s >= NN || (unsigned)d >= NN) return;
    if (s != d) {
        atomicAdd(&g_deg[s], 1);
        atomicAdd(&g_cnt[d], 1);
    }
}

__global__ void dinv_k() {
    int i = blockIdx.x * blockDim.x + threadIdx.x;
    if (i >= NN) return;
    int d = g_deg[i];
    g_dinv[i] = (d > 0) ? rsqrtf((float)d) : 0.0f;
}

__global__ void scan_block_k() {
    __shared__ int sh[1024];
    int i = blockIdx.x * 1024 + threadIdx.x;
    int v = (i < NN) ? g_cnt[i] : 0;
    sh[threadIdx.x] = v;
    __syncthreads();
    for (int off = 1; off < 1024; off <<= 1) {
        int t = (threadIdx.x >= off) ? sh[threadIdx.x - off] : 0;
        __syncthreads();
        sh[threadIdx.x] += t;
        __syncthreads();
    }
    if (i < NN) g_rowptr[i] = sh[threadIdx.x] - v;
    if (threadIdx.x == 1023) g_bsum[blockIdx.x] = sh[1023];
}

__global__ void scan_top_k(int nb) {
    if (threadIdx.x == 0) {
        int run = 0;
        for (int b = 0; b < nb; b++) { int t = g_bsum[b]; g_bsum[b] = run; run += t; }
        g_total[0] = run;
    }
}

__global__ void scan_add_k() {
    int i = blockIdx.x * blockDim.x + threadIdx.x;
    if (i < NN) {
        int v = g_rowptr[i] + g_bsum[i >> 10];
        g_rowptr[i] = v;
        g_fill[i] = v;
    }
    if (i == NN) g_rowptr[NN] = g_total[0];
}

__global__ void scatter_k(const int* __restrict__ ei32) {
    int e = blockIdx.x * blockDim.x + threadIdx.x;
    if (e >= EE) return;
    int s, d;
    load_edge(ei32, e, s, d);
    if ((unsigned)s >= NN || (unsigned)d >= NN) return;
    if (s == d) return;
    int pos = atomicAdd(&g_fill[d], 1);
    g_col[pos] = s;
    g_w[pos] = -g_dinv[s] * g_dinv[d];
}

// ---------------- fp32 -> fp16 conversion ----------------

__global__ void conv_f2h_k(const float* __restrict__ src, int dst_h, int total) {
    __half* __restrict__ D = hbuf(dst_h);
    int i = blockIdx.x * blockDim.x + threadIdx.x;
    if (i < total) D[i] = __float2half(src[i]);
}

// ---------------- sparse propagation (F = 128, warp per dst row, fp16 storage) ----

__global__ void prop_first_h(int x_h, int y_h) {
    const __half* __restrict__ X = hbuf(x_h);
    __half* __restrict__ Y = hbuf(y_h);
    int wid = (blockIdx.x * blockDim.x + threadIdx.x) >> 5;
    int lane = threadIdx.x & 31;
    if (wid >= NN) return;
    int beg = g_rowptr[wid], end = g_rowptr[wid + 1];
    float ax = 0.f, ay = 0.f, az = 0.f, aw = 0.f;
#pragma unroll 4
    for (int e = beg; e < end; e++) {
        int s = g_col[e];
        float w = g_w[e];
        uint2 u = ((const uint2*)(X + (size_t)s * 128))[lane];
        float2 f0 = __half22float2(*(__half2*)&u.x);
        float2 f1 = __half22float2(*(__half2*)&u.y);
        ax = fmaf(w, f0.x, ax);
        ay = fmaf(w, f0.y, ay);
        az = fmaf(w, f1.x, az);
        aw = fmaf(w, f1.y, aw);
    }
    uint2 o;
    *(__half2*)&o.x = __floats2half2_rn(ax, ay);
    *(__half2*)&o.y = __floats2half2_rn(az, aw);
    ((uint2*)(Y + (size_t)wid * 128))[lane] = o;
}

__global__ void prop_rec_h(int x1_h, int x0_h, int y_h) {
    const __half* __restrict__ X1 = hbuf(x1_h);
    const __half* __restrict__ X0 = hbuf(x0_h);
    __half* __restrict__ Y = hbuf(y_h);
    int wid = (blockIdx.x * blockDim.x + threadIdx.x) >> 5;
    int lane = threadIdx.x & 31;
    if (wid >= NN) return;
    int beg = g_rowptr[wid], end = g_rowptr[wid + 1];
    float ax = 0.f, ay = 0.f, az = 0.f, aw = 0.f;
#pragma unroll 4
    for (int e = beg; e < end; e++) {
        int s = g_col[e];
        float w = g_w[e];
        uint2 u = ((const uint2*)(X1 + (size_t)s * 128))[lane];
        float2 f0 = __half22float2(*(__half2*)&u.x);
        float2 f1 = __half22float2(*(__half2*)&u.y);
        ax = fmaf(w, f0.x, ax);
        ay = fmaf(w, f0.y, ay);
        az = fmaf(w, f1.x, az);
        aw = fmaf(w, f1.y, aw);
    }
    uint2 p = ((const uint2*)(X0 + (size_t)wid * 128))[lane];
    float2 p0 = __half22float2(*(__half2*)&p.x);
    float2 p1 = __half22float2(*(__half2*)&p.y);
    uint2 o;
    *(__half2*)&o.x = __floats2half2_rn(2.f * ax - p0.x, 2.f * ay - p0.y);
    *(__half2*)&o.y = __floats2half2_rn(2.f * az - p1.x, 2.f * aw - p1.y);
    ((uint2*)(Y + (size_t)wid * 128))[lane] = o;
}

// ---------------- GEMMs: C[n x FO] = (ACC ? C : 0) + A[n x 128] * B[128 x FO] ----
// HA=1: A is fp16 hbuf(a_idx); HA=0: A is fp32 (ext ptr if a_idx<0 else fbuf)

template <int ACC, int HA>
__global__ void gemm128_k(const float* __restrict__ Aext, int a_idx,
                          const float* __restrict__ B, int c_idx, int n) {
    const float* __restrict__ Af = HA ? nullptr : ((a_idx < 0) ? Aext : fbuf(a_idx));
    const __half* __restrict__ Ah = HA ? hbuf(a_idx) : nullptr;
    float* __restrict__ C = fbuf(c_idx);
    const int m0 = blockIdx.x * 64;
    __shared__ float As[16][65];
    __shared__ float Bs[16][128];
    const int tid = threadIdx.x;
    const int ty = tid >> 4;
    const int tx = tid & 15;
    float acc[8][8];
#pragma unroll
    for (int r = 0; r < 8; r++)
#pragma unroll
        for (int c = 0; c < 8; c++) acc[r][c] = 0.f;

    for (int kk = 0; kk < 128; kk += 16) {
#pragma unroll
        for (int i = tid; i < 64 * 16; i += 128) {
            int m = i >> 4, t = i & 15;
            int row = m0 + m;
            float v = 0.f;
            if (row < n)
                v = HA ? __half2float(Ah[(size_t)row * 128 + kk + t])
                       : Af[(size_t)row * 128 + kk + t];
            As[t][m] = v;
        }
#pragma unroll
        for (int i = tid; i < 16 * 128; i += 128) {
            int t = i >> 7, c = i & 127;
            Bs[t][c] = B[(size_t)(kk + t) * 128 + c];
        }
        __syncthreads();
#pragma unroll
        for (int t = 0; t < 16; t++) {
            float a[8], b[8];
#pragma unroll
            for (int r = 0; r < 8; r++) a[r] = As[t][ty * 8 + r];
#pragma unroll
            for (int c = 0; c < 8; c++) b[c] = Bs[t][tx * 8 + c];
#pragma unroll
            for (int r = 0; r < 8; r++)
#pragma unroll
                for (int c = 0; c < 8; c++)
                    acc[r][c] = fmaf(a[r], b[c], acc[r][c]);
        }
        __syncthreads();
    }
#pragma unroll
    for (int r = 0; r < 8; r++) {
        int row = m0 + ty * 8 + r;
        if (row < n) {
#pragma unroll
            for (int c = 0; c < 8; c += 4) {
                float4* p = (float4*)&C[(size_t)row * 128 + tx * 8 + c];
                float4 v;
                if (ACC) {
                    v = *p;
                    v.x += acc[r][c + 0];
                    v.y += acc[r][c + 1];
                    v.z += acc[r][c + 2];
                    v.w += acc[r][c + 3];
                } else {
                    v.x = acc[r][c + 0];
                    v.y = acc[r][c + 1];
                    v.z = acc[r][c + 2];
                    v.w = acc[r][c + 3];
                }
                *p = v;
            }
        }
    }
}

template <int ACC, int HA>
__global__ void gemm32_k(const float* __restrict__ Aext, int a_idx,
                         const float* __restrict__ B, int c_idx, int n) {
    const float* __restrict__ Af = HA ? nullptr : ((a_idx < 0) ? Aext : fbuf(a_idx));
    const __half* __restrict__ Ah = HA ? hbuf(a_idx) : nullptr;
    float* __restrict__ C = fbuf(c_idx);
    const int m0 = blockIdx.x * 128;
    __shared__ float As[16][129];
    __shared__ float Bs[16][33];
    const int tid = threadIdx.x;
    const int ty = tid >> 3;
    const int tx = tid & 7;
    float acc[8][4];
#pragma unroll
    for (int r = 0; r < 8; r++)
#pragma unroll
        for (int c = 0; c < 4; c++) acc[r][c] = 0.f;

    for (int kk = 0; kk < 128; kk += 16) {
#pragma unroll
        for (int i = tid; i < 128 * 16; i += 128) {
            int m = i >> 4, t = i & 15;
            int row = m0 + m;
            float v = 0.f;
            if (row < n)
                v = HA ? __half2float(Ah[(size_t)row * 128 + kk + t])
                       : Af[(size_t)row * 128 + kk + t];
            As[t][m] = v;
        }
#pragma unroll
        for (int i = tid; i < 16 * 32; i += 128) {
            int t = i >> 5, c = i & 31;
            Bs[t][c] = B[(size_t)(kk + t) * 32 + c];
        }
        __syncthreads();
#pragma unroll
        for (int t = 0; t < 16; t++) {
            float a[8], b[4];
#pragma unroll
            for (int r = 0; r < 8; r++) a[r] = As[t][ty * 8 + r];
#pragma unroll
            for (int c = 0; c < 4; c++) b[c] = Bs[t][tx * 4 + c];
#pragma unroll
            for (int r = 0; r < 8; r++)
#pragma unroll
                for (int c = 0; c < 4; c++)
                    acc[r][c] = fmaf(a[r], b[c], acc[r][c]);
        }
        __syncthreads();
    }
#pragma unroll
    for (int r = 0; r < 8; r++) {
        int row = m0 + ty * 8 + r;
        if (row < n) {
            float4* p = (float4*)&C[(size_t)row * 32 + tx * 4];
            float4 v;
            if (ACC) {
                v = *p;
                v.x += acc[r][0];
                v.y += acc[r][1];
                v.z += acc[r][2];
                v.w += acc[r][3];
            } else {
                v.x = acc[r][0];
                v.y = acc[r][1];
                v.z = acc[r][2];
                v.w = acc[r][3];
            }
            *p = v;
        }
    }
}

// ---------------- BatchNorm (training-mode) + ReLU ----------------

__global__ void bn_stats_k(int v_idx, int total, int F) {
    const float* __restrict__ V = fbuf(v_idx);
    int idx = blockIdx.x * blockDim.x + threadIdx.x;
    int stride = gridDim.x * blockDim.x;
    float s = 0.f, s2 = 0.f;
    int col = idx % F;
    for (int i = idx; i < total; i += stride) {
        float v = V[i];
        s += v;
        s2 = fmaf(v, v, s2);
    }
    atomicAdd(&g_stats[col], s);
    atomicAdd(&g_stats[F + col], s2);
}

__global__ void bn_finalize_k(const float* __restrict__ gamma,
                              const float* __restrict__ beta, int F, float invN) {
    int c = threadIdx.x;
    if (c < F) {
        float mu = g_stats[c] * invN;
        float var = g_stats[F + c] * invN - mu * mu;
        float sc = gamma[c] * rsqrtf(var + BN_EPS);
        g_stats[c] = sc;
        g_stats[F + c] = beta[c] - sc * mu;
    }
}

// Applies BN+ReLU. Writes fp32 to (Yext if y_idx<0 else fbuf(y_idx)); if
// yh_idx >= 0 also writes an fp16 copy to hbuf(yh_idx) for the next gather.
__global__ void bn_apply_k(int v_idx, float* __restrict__ Yext, int y_idx,
                           int yh_idx, int total, int F) {
    const float* __restrict__ V = fbuf(v_idx);
    float* __restrict__ Y = (y_idx < 0) ? Yext : fbuf(y_idx);
    int idx = blockIdx.x * blockDim.x + threadIdx.x;
    if (idx >= total) return;
    int c = idx % F;
    float y = fmaf(g_stats[c], V[idx], g_stats[F + c]);
    y = fmaxf(y, 0.f);
    Y[idx] = y;
    if (yh_idx >= 0) hbuf(yh_idx)[idx] = __float2half(y);
}

// ---------------- host launch: kernel launches ONLY ----------------

extern "C" void kernel_launch(void* const* d_in, const int* in_sizes, int n_in,
                              void* d_out, int out_size) {
    const float* x  = (const float*)d_in[0];
    const int* ei32 = (const int*)d_in[1];
    const float* W1 = (const float*)d_in[2];
    const float* W2 = (const float*)d_in[4];
    const float* g1 = (const float*)d_in[6];
    const float* be1 = (const float*)d_in[7];
    const float* g2 = (const float*)d_in[8];
    const float* be2 = (const float*)d_in[9];
    float* out = (float*)d_out;

    // half buffers: 0=TxA 1=TxB 2=TxC 3=xh 4=hh ; float buffers: 0=out1 1=h 2=out2
    const int HA_ = 0, HB_ = 1, HC_ = 2, HX = 3, HH = 4;
    const int FO1 = 0, FH = 1, FO2 = 2, EXT = -1;

    // --- edge dtype detection + graph preprocessing -> CSR with weights ---
    detect_init_k<<<1, 32>>>();
    detect_k<<<16, 256>>>(ei32);
    zero_graph_k<<<(NN + 255) / 256, 256>>>();
    deg_count_k<<<(EE + 255) / 256, 256>>>(ei32);
    dinv_k<<<(NN + 255) / 256, 256>>>();
    int nb = (NN + 1023) / 1024;
    scan_block_k<<<nb, 1024>>>();
    scan_top_k<<<1, 32>>>(nb);
    scan_add_k<<<(NN + 1 + 255) / 256, 256>>>();
    scatter_k<<<(EE + 255) / 256, 256>>>(ei32);

    const int PROP_GRID = (NN * 32 + 255) / 256;
    const int G128 = (NN + 63) / 64;
    const int G32 = (NN + 127) / 128;

    // --- layer 1: ChebConv(128 -> 128) ---
    conv_f2h_k<<<(NN * 128 + 255) / 256, 256>>>(x, HX, NN * 128);
    gemm128_k<0, 0><<<G128, 128>>>(x, EXT, W1, FO1, NN);          // k=0 exact fp32
    prop_first_h<<<PROP_GRID, 256>>>(HX, HA_);
    gemm128_k<1, 1><<<G128, 128>>>(nullptr, HA_, W1 + 1 * 128 * 128, FO1, NN);
    {
        int pp = HX, p1 = HA_;
        const int bufs[3] = {HA_, HB_, HC_};
        int bi = 1;
        for (int k = 2; k < K_CHEB; k++) {
            int dst = bufs[bi];
            bi = (bi + 1) % 3;
            prop_rec_h<<<PROP_GRID, 256>>>(p1, pp, dst);
            gemm128_k<1, 1><<<G128, 128>>>(nullptr, dst, W1 + (size_t)k * 128 * 128, FO1, NN);
            pp = p1;
            p1 = dst;
        }
    }
    // BN + ReLU (bias cancels in BN mean subtraction); writes fp32 h + fp16 hh
    zero_stats_k<<<1, 256>>>();
    bn_stats_k<<<256, 256>>>(FO1, NN * 128, 128);
    bn_finalize_k<<<1, 128>>>(g1, be1, 128, 1.0f / NN);
    bn_apply_k<<<(NN * 128 + 255) / 256, 256>>>(FO1, nullptr, FH, HH, NN * 128, 128);

    // --- layer 2: ChebConv(128 -> 32) ---
    gemm32_k<0, 0><<<G32, 128>>>(nullptr, FH, W2, FO2, NN);       // k=0 exact fp32
    prop_first_h<<<PROP_GRID, 256>>>(HH, HA_);
    gemm32_k<1, 1><<<G32, 128>>>(nullptr, HA_, W2 + 1 * 128 * 32, FO2, NN);
    {
        int pp = HH, p1 = HA_;
        const int bufs[3] = {HA_, HB_, HC_};
        int bi = 1;
        for (int k = 2; k < K_CHEB; k++) {
            int dst = bufs[bi];
            bi = (bi + 1) % 3;
            prop_rec_h<<<PROP_GRID, 256>>>(p1, pp, dst);
            gemm32_k<1, 1><<<G32, 128>>>(nullptr, dst, W2 + (size_t)k * 128 * 32, FO2, NN);
            pp = p1;
            p1 = dst;
        }
    }
    zero_stats_k<<<1, 256>>>();
    bn_stats_k<<<256, 256>>>(FO2, NN * 32, 32);
    bn_finalize_k<<<1, 32>>>(g2, be2, 32, 1.0f / NN);
    bn_apply_k<<<(NN * 32 + 255) / 256, 256>>>(FO2, out, EXT, -1, NN * 32, 32);
}

// round 6
// speedup vs baseline: 1.9052x; 1.7441x over previous
#include <cuda_runtime.h>
#include <cuda_fp16.h>
#include <mma.h>
using namespace nvcuda;

// Problem constants
#define NN 50000
#define EE 800000
#define K_CHEB 16
#define BN_EPS 1e-5f

// ---------------- scratch (device globals; no allocation allowed) ----------------
__device__ int   g_is64;
__device__ int   g_deg[NN];
__device__ float g_dinv[NN];
__device__ int   g_cnt[NN];
__device__ int   g_rowptr[NN + 1];
__device__ int   g_fill[NN];
__device__ int   g_col[EE];
__device__ float g_w[EE];
__device__ int   g_bsum[64];
__device__ int   g_total[1];

// Big fp16 buffer holding all 16 Chebyshev terms (GEMM A operand + gather source)
__device__ __half g_big[(size_t)K_CHEB * NN * 128];       // 204.8 MB
// fp16 weights for tensor-core GEMM
__device__ __half g_W1h[16 * 128 * 128];
__device__ __half g_W2h[16 * 128 * 32];
// fp32 recurrence chain ping-pong + layer outputs
__device__ float g_TxA[(size_t)NN * 128];
__device__ float g_TxB[(size_t)NN * 128];
__device__ float g_TxC[(size_t)NN * 128];
__device__ float g_h[(size_t)NN * 128];
__device__ float g_out1[(size_t)NN * 128];
__device__ float g_out2[(size_t)NN * 32];
__device__ float g_stats[2 * 128];

// float buffers: 0=TxA 1=TxB 2=TxC 3=h 4=out1 5=out2
__device__ __forceinline__ float* fbuf(int i) {
    switch (i) {
        case 0: return g_TxA;
        case 1: return g_TxB;
        case 2: return g_TxC;
        case 3: return g_h;
        case 4: return g_out1;
        default: return g_out2;
    }
}

// ---------------- edge dtype detection ----------------

__global__ void detect_init_k() { if (threadIdx.x == 0) g_is64 = 1; }

__global__ void detect_k(const int* __restrict__ ei32) {
    int e = blockIdx.x * blockDim.x + threadIdx.x;
    if (e >= 4096) return;
    if (ei32[2 * e + 1] != 0) g_is64 = 0;
}

__device__ __forceinline__ void load_edge(const int* __restrict__ ei32, int e,
                                          int& s, int& d) {
    if (g_is64) { s = ei32[2 * e]; d = ei32[2 * (EE + e)]; }
    else        { s = ei32[e];     d = ei32[EE + e]; }
}

// ---------------- zero-init ----------------

__global__ void zero_graph_k() {
    int i = blockIdx.x * blockDim.x + threadIdx.x;
    if (i < NN) { g_deg[i] = 0; g_cnt[i] = 0; }
}

__global__ void zero_stats_k() {
    int i = threadIdx.x;
    if (i < 2 * 128) g_stats[i] = 0.f;
}

// ---------------- graph preprocessing ----------------

__global__ void deg_count_k(const int* __restrict__ ei32) {
    int e = blockIdx.x * blockDim.x + threadIdx.x;
    if (e >= EE) return;
    int s, d;
    load_edge(ei32, e, s, d);
    if ((unsigned)s >= NN || (unsigned)d >= NN) return;
    if (s != d) { atomicAdd(&g_deg[s], 1); atomicAdd(&g_cnt[d], 1); }
}

__global__ void dinv_k() {
    int i = blockIdx.x * blockDim.x + threadIdx.x;
    if (i >= NN) return;
    int d = g_deg[i];
    g_dinv[i] = (d > 0) ? rsqrtf((float)d) : 0.0f;
}

__global__ void scan_block_k() {
    __shared__ int sh[1024];
    int i = blockIdx.x * 1024 + threadIdx.x;
    int v = (i < NN) ? g_cnt[i] : 0;
    sh[threadIdx.x] = v;
    __syncthreads();
    for (int off = 1; off < 1024; off <<= 1) {
        int t = (threadIdx.x >= off) ? sh[threadIdx.x - off] : 0;
        __syncthreads();
        sh[threadIdx.x] += t;
        __syncthreads();
    }
    if (i < NN) g_rowptr[i] = sh[threadIdx.x] - v;
    if (threadIdx.x == 1023) g_bsum[blockIdx.x] = sh[1023];
}

__global__ void scan_top_k(int nb) {
    if (threadIdx.x == 0) {
        int run = 0;
        for (int b = 0; b < nb; b++) { int t = g_bsum[b]; g_bsum[b] = run; run += t; }
        g_total[0] = run;
    }
}

__global__ void scan_add_k() {
    int i = blockIdx.x * blockDim.x + threadIdx.x;
    if (i < NN) {
        int v = g_rowptr[i] + g_bsum[i >> 10];
        g_rowptr[i] = v;
        g_fill[i] = v;
    }
    if (i == NN) g_rowptr[NN] = g_total[0];
}

__global__ void scatter_k(const int* __restrict__ ei32) {
    int e = blockIdx.x * blockDim.x + threadIdx.x;
    if (e >= EE) return;
    int s, d;
    load_edge(ei32, e, s, d);
    if ((unsigned)s >= NN || (unsigned)d >= NN) return;
    if (s == d) return;
    int pos = atomicAdd(&g_fill[d], 1);
    g_col[pos] = s;
    g_w[pos] = -g_dinv[s] * g_dinv[d];
}

// ---------------- conversions ----------------

__global__ void conv_x_k(const float* __restrict__ x) {   // x -> slice 0 fp16
    int i = blockIdx.x * blockDim.x + threadIdx.x;
    if (i < NN * 128) g_big[i] = __float2half(x[i]);
}

__global__ void conv_w_k(const float* __restrict__ W1, const float* __restrict__ W2) {
    int i = blockIdx.x * blockDim.x + threadIdx.x;
    if (i < 16 * 128 * 128) g_W1h[i] = __float2half(W1[i]);
    if (i < 16 * 128 * 32)  g_W2h[i] = __float2half(W2[i]);
}

// ---------------- sparse propagation (warp per dst row) ----------------
// Gather from fp16 slice; X0 from fp32; write fp32 chain + fp16 slice.

__global__ void prop_first2_k(int x_slice, int y_f, int y_slice) {
    const __half* __restrict__ X = g_big + (size_t)x_slice * NN * 128;
    float* __restrict__ Yf = fbuf(y_f);
    __half* __restrict__ Yh = g_big + (size_t)y_slice * NN * 128;
    int wid = (blockIdx.x * blockDim.x + threadIdx.x) >> 5;
    int lane = threadIdx.x & 31;
    if (wid >= NN) return;
    int beg = g_rowptr[wid], end = g_rowptr[wid + 1];
    float ax = 0.f, ay = 0.f, az = 0.f, aw = 0.f;
#pragma unroll 4
    for (int e = beg; e < end; e++) {
        int s = g_col[e];
        float w = g_w[e];
        uint2 u = ((const uint2*)(X + (size_t)s * 128))[lane];
        float2 f0 = __half22float2(*(__half2*)&u.x);
        float2 f1 = __half22float2(*(__half2*)&u.y);
        ax = fmaf(w, f0.x, ax);
        ay = fmaf(w, f0.y, ay);
        az = fmaf(w, f1.x, az);
        aw = fmaf(w, f1.y, aw);
    }
    ((float4*)(Yf + (size_t)wid * 128))[lane] = make_float4(ax, ay, az, aw);
    uint2 o;
    *(__half2*)&o.x = __floats2half2_rn(ax, ay);
    *(__half2*)&o.y = __floats2half2_rn(az, aw);
    ((uint2*)(Yh + (size_t)wid * 128))[lane] = o;
}

__global__ void prop_rec2_k(const float* __restrict__ x0ext, int x0_f,
                            int x1_slice, int y_f, int y_slice) {
    const __half* __restrict__ X1 = g_big + (size_t)x1_slice * NN * 128;
    const float* __restrict__ X0 = (x0_f < 0) ? x0ext : fbuf(x0_f);
    float* __restrict__ Yf = fbuf(y_f);
    __half* __restrict__ Yh = g_big + (size_t)y_slice * NN * 128;
    int wid = (blockIdx.x * blockDim.x + threadIdx.x) >> 5;
    int lane = threadIdx.x & 31;
    if (wid >= NN) return;
    int beg = g_rowptr[wid], end = g_rowptr[wid + 1];
    float ax = 0.f, ay = 0.f, az = 0.f, aw = 0.f;
#pragma unroll 4
    for (int e = beg; e < end; e++) {
        int s = g_col[e];
        float w = g_w[e];
        uint2 u = ((const uint2*)(X1 + (size_t)s * 128))[lane];
        float2 f0 = __half22float2(*(__half2*)&u.x);
        float2 f1 = __half22float2(*(__half2*)&u.y);
        ax = fmaf(w, f0.x, ax);
        ay = fmaf(w, f0.y, ay);
        az = fmaf(w, f1.x, az);
        aw = fmaf(w, f1.y, aw);
    }
    float4 p = ((const float4*)(X0 + (size_t)wid * 128))[lane];
    float ox = 2.f * ax - p.x;
    float oy = 2.f * ay - p.y;
    float oz = 2.f * az - p.z;
    float ow = 2.f * aw - p.w;
    ((float4*)(Yf + (size_t)wid * 128))[lane] = make_float4(ox, oy, oz, ow);
    uint2 o;
    *(__half2*)&o.x = __floats2half2_rn(ox, oy);
    *(__half2*)&o.y = __floats2half2_rn(oz, ow);
    ((uint2*)(Yh + (size_t)wid * 128))[lane] = o;
}

// ---------------- fused tensor-core GEMMs over K = 16*128 = 2048 ----------------
// out1[NN,128] = g_big[16 slices NN x128] * W1h[2048 x 128]
// 256 threads = 8 warps; block tile 128 rows; warp tile 16 rows x 128 cols.

__global__ void gemm_tc128_k(int n) {
    const int warp = threadIdx.x >> 5;
    const int row0 = blockIdx.x * 128 + warp * 16;
    __shared__ __align__(32) __half Bs[16 * 128];
    wmma::fragment<wmma::accumulator, 16, 16, 16, float> acc[8];
#pragma unroll
    for (int i = 0; i < 8; i++) wmma::fill_fragment(acc[i], 0.f);

    for (int kc = 0; kc < 128; kc++) {          // 2048 / 16 chunks
        // stage B chunk [16 x 128] fp16: 2048 halfs = 256 uint4
        ((uint4*)Bs)[threadIdx.x] = ((const uint4*)(g_W1h + (size_t)kc * 16 * 128))[threadIdx.x];
        __syncthreads();
        if (row0 < n) {
            int slice = kc >> 3;                 // 8 chunks per 128-wide slice
            int f0 = (kc & 7) * 16;
            const __half* Ag = g_big + (size_t)slice * NN * 128 + (size_t)row0 * 128 + f0;
            wmma::fragment<wmma::matrix_a, 16, 16, 16, __half, wmma::row_major> a;
            wmma::load_matrix_sync(a, Ag, 128);
#pragma unroll
            for (int nf = 0; nf < 8; nf++) {
                wmma::fragment<wmma::matrix_b, 16, 16, 16, __half, wmma::row_major> b;
                wmma::load_matrix_sync(b, Bs + nf * 16, 128);
                wmma::mma_sync(acc[nf], a, b, acc[nf]);
            }
        }
        __syncthreads();
    }
    if (row0 < n) {
#pragma unroll
        for (int nf = 0; nf < 8; nf++)
            wmma::store_matrix_sync(g_out1 + (size_t)row0 * 128 + nf * 16, acc[nf],
                                    128, wmma::mem_row_major);
    }
}

// out2[NN,32] = g_big * W2h[2048 x 32]
__global__ void gemm_tc32_k(int n) {
    const int warp = threadIdx.x >> 5;
    const int row0 = blockIdx.x * 128 + warp * 16;
    __shared__ __align__(32) __half Bs[16 * 32];
    wmma::fragment<wmma::accumulator, 16, 16, 16, float> acc[2];
#pragma unroll
    for (int i = 0; i < 2; i++) wmma::fill_fragment(acc[i], 0.f);

    for (int kc = 0; kc < 128; kc++) {
        if (threadIdx.x < 64)                    // 512 halfs = 64 uint4
            ((uint4*)Bs)[threadIdx.x] = ((const uint4*)(g_W2h + (size_t)kc * 16 * 32))[threadIdx.x];
        __syncthreads();
        if (row0 < n) {
            int slice = kc >> 3;
            int f0 = (kc & 7) * 16;
            const __half* Ag = g_big + (size_t)slice * NN * 128 + (size_t)row0 * 128 + f0;
            wmma::fragment<wmma::matrix_a, 16, 16, 16, __half, wmma::row_major> a;
            wmma::load_matrix_sync(a, Ag, 128);
#pragma unroll
            for (int nf = 0; nf < 2; nf++) {
                wmma::fragment<wmma::matrix_b, 16, 16, 16, __half, wmma::row_major> b;
                wmma::load_matrix_sync(b, Bs + nf * 16, 32);
                wmma::mma_sync(acc[nf], a, b, acc[nf]);
            }
        }
        __syncthreads();
    }
    if (row0 < n) {
#pragma unroll
        for (int nf = 0; nf < 2; nf++)
            wmma::store_matrix_sync(g_out2 + (size_t)row0 * 32 + nf * 16, acc[nf],
                                    32, wmma::mem_row_major);
    }
}

// ---------------- BatchNorm (training-mode) + ReLU ----------------

__global__ void bn_stats_k(int v_f, int total, int F) {
    const float* __restrict__ V = fbuf(v_f);
    int idx = blockIdx.x * blockDim.x + threadIdx.x;
    int stride = gridDim.x * blockDim.x;
    float s = 0.f, s2 = 0.f;
    int col = idx % F;
    for (int i = idx; i < total; i += stride) {
        float v = V[i];
        s += v;
        s2 = fmaf(v, v, s2);
    }
    atomicAdd(&g_stats[col], s);
    atomicAdd(&g_stats[F + col], s2);
}

__global__ void bn_finalize_k(const float* __restrict__ gamma,
                              const float* __restrict__ beta, int F, float invN) {
    int c = threadIdx.x;
    if (c < F) {
        float mu = g_stats[c] * invN;
        float var = g_stats[F + c] * invN - mu * mu;
        float sc = gamma[c] * rsqrtf(var + BN_EPS);
        g_stats[c] = sc;
        g_stats[F + c] = beta[c] - sc * mu;
    }
}

// BN+ReLU; fp32 out to (Yext if y_f<0 else fbuf); optional fp16 copy into slice.
__global__ void bn_apply_k(int v_f, float* __restrict__ Yext, int y_f,
                           int yh_slice, int total, int F) {
    const float* __restrict__ V = fbuf(v_f);
    float* __restrict__ Y = (y_f < 0) ? Yext : fbuf(y_f);
    int idx = blockIdx.x * blockDim.x + threadIdx.x;
    if (idx >= total) return;
    int c = idx % F;
    float y = fmaf(g_stats[c], V[idx], g_stats[F + c]);
    y = fmaxf(y, 0.f);
    Y[idx] = y;
    if (yh_slice >= 0) g_big[(size_t)yh_slice * NN * 128 + idx] = __float2half(y);
}

// ---------------- host launch: kernel launches ONLY ----------------

extern "C" void kernel_launch(void* const* d_in, const int* in_sizes, int n_in,
                              void* d_out, int out_size) {
    const float* x  = (const float*)d_in[0];
    const int* ei32 = (const int*)d_in[1];
    const float* W1 = (const float*)d_in[2];
    const float* W2 = (const float*)d_in[4];
    const float* g1 = (const float*)d_in[6];
    const float* be1 = (const float*)d_in[7];
    const float* g2 = (const float*)d_in[8];
    const float* be2 = (const float*)d_in[9];
    float* out = (float*)d_out;

    // float buffers: 0=TxA 1=TxB 2=TxC 3=h 4=out1 5=out2 ; -1 = external
    const int FA = 0, FB = 1, FC = 2, FH = 3, FO1 = 4, FO2 = 5, EXT = -1;

    // --- preprocessing ---
    detect_init_k<<<1, 32>>>();
    detect_k<<<16, 256>>>(ei32);
    zero_graph_k<<<(NN + 255) / 256, 256>>>();
    deg_count_k<<<(EE + 255) / 256, 256>>>(ei32);
    dinv_k<<<(NN + 255) / 256, 256>>>();
    int nb = (NN + 1023) / 1024;
    scan_block_k<<<nb, 1024>>>();
    scan_top_k<<<1, 32>>>(nb);
    scan_add_k<<<(NN + 1 + 255) / 256, 256>>>();
    scatter_k<<<(EE + 255) / 256, 256>>>(ei32);
    conv_w_k<<<(16 * 128 * 128 + 255) / 256, 256>>>(W1, W2);

    const int PROP_GRID = (NN * 32 + 255) / 256;
    const int GT = (NN + 127) / 128;   // tensor GEMM grid (128 rows/block)

    // --- layer 1: ChebConv(128 -> 128) ---
    conv_x_k<<<(NN * 128 + 255) / 256, 256>>>(x);             // slice 0 = fp16(x)
    prop_first2_k<<<PROP_GRID, 256>>>(0, FA, 1);              // Tx1
    {
        int pp = EXT, p1 = FA;                                 // fp32 chain: X0, X1
        const int bufs[3] = {FA, FB, FC};
        int bi = 1;
        for (int k = 2; k < K_CHEB; k++) {
            int dst = bufs[bi];
            bi = (bi + 1) % 3;
            prop_rec2_k<<<PROP_GRID, 256>>>(x, pp, k - 1, dst, k);
            pp = p1;
            p1 = dst;
        }
    }
    gemm_tc128_k<<<GT, 256>>>(NN);                             // fused K=2048 GEMM
    zero_stats_k<<<1, 256>>>();
    bn_stats_k<<<256, 256>>>(FO1, NN * 128, 128);
    bn_finalize_k<<<1, 128>>>(g1, be1, 128, 1.0f / NN);
    bn_apply_k<<<(NN * 128 + 255) / 256, 256>>>(FO1, nullptr, FH, 0, NN * 128, 128);

    // --- layer 2: ChebConv(128 -> 32) ---
    prop_first2_k<<<PROP_GRID, 256>>>(0, FA, 1);
    {
        int pp = FH, p1 = FA;
        const int bufs[3] = {FA, FB, FC};
        int bi = 1;
        for (int k = 2; k < K_CHEB; k++) {
            int dst = bufs[bi];
            bi = (bi + 1) % 3;
            prop_rec2_k<<<PROP_GRID, 256>>>(nullptr, pp, k - 1, dst, k);
            pp = p1;
            p1 = dst;
        }
    }
    gemm_tc32_k<<<GT, 256>>>(NN);
    zero_stats_k<<<1, 256>>>();
    bn_stats_k<<<256, 256>>>(FO2, NN * 32, 32);
    bn_finalize_k<<<1, 32>>>(g2, be2, 32, 1.0f / NN);
    bn_apply_k<<<(NN * 32 + 255) / 256, 256>>>(FO2, out, EXT, -1, NN * 32, 32);
}

// round 7
// speedup vs baseline: 2.0858x; 1.0948x over previous
#include <cuda_runtime.h>
#include <cuda_fp16.h>
#include <mma.h>
using namespace nvcuda;

// Problem constants
#define NN 50000
#define EE 800000
#define K_CHEB 16
#define BN_EPS 1e-5f

// ---------------- scratch (device globals; no allocation allowed) ----------------
__device__ int   g_is64;
__device__ int   g_deg[NN];
__device__ float g_dinv[NN];
__device__ int   g_cnt[NN];
__device__ int   g_rowptr[NN + 1];
__device__ int   g_fill[NN];
__device__ int   g_col[EE];
__device__ float g_w[EE];
__device__ int   g_bsum[64];
__device__ int   g_total[1];

// Big fp16 buffer holding all 16 Chebyshev terms for layer 1 (+ h in slice 0)
__device__ __half g_big[(size_t)K_CHEB * NN * 128];       // 204.8 MB
// fp16 weights
__device__ __half g_W1h[16 * 128 * 128];
__device__ __half g_W2t[128 * 512];                       // W2t[f][k*32+c] = W2[k][f][c]
// fp32 recurrence chain ping-pong (layer 1) + layer outputs
__device__ float g_TxA[(size_t)NN * 128];
__device__ float g_TxB[(size_t)NN * 128];
__device__ float g_TxC[(size_t)NN * 128];
__device__ float g_out1[(size_t)NN * 128];
__device__ float g_out2[(size_t)NN * 32];
__device__ float g_stats[2 * 128];
// Layer-2 Clenshaw: P[k][N][32] fp32, B chain fp32 + fp16 gather mirrors
__device__ float  g_P[(size_t)16 * NN * 32];              // 102.4 MB
__device__ float  g_Bf[3][(size_t)NN * 32];
__device__ __half g_Bh[3][(size_t)NN * 32];

// float buffers: 0=TxA 1=TxB 2=TxC 3=out1 4=out2
__device__ __forceinline__ float* fbuf(int i) {
    switch (i) {
        case 0: return g_TxA;
        case 1: return g_TxB;
        case 2: return g_TxC;
        case 3: return g_out1;
        default: return g_out2;
    }
}

// ---------------- edge dtype detection ----------------

__global__ void detect_init_k() { if (threadIdx.x == 0) g_is64 = 1; }

__global__ void detect_k(const int* __restrict__ ei32) {
    int e = blockIdx.x * blockDim.x + threadIdx.x;
    if (e >= 4096) return;
    if (ei32[2 * e + 1] != 0) g_is64 = 0;
}

__device__ __forceinline__ void load_edge(const int* __restrict__ ei32, int e,
                                          int& s, int& d) {
    if (g_is64) { s = ei32[2 * e]; d = ei32[2 * (EE + e)]; }
    else        { s = ei32[e];     d = ei32[EE + e]; }
}

// ---------------- zero-init ----------------

__global__ void zero_graph_k() {
    int i = blockIdx.x * blockDim.x + threadIdx.x;
    if (i < NN) { g_deg[i] = 0; g_cnt[i] = 0; }
}

__global__ void zero_stats_k() {
    int i = threadIdx.x;
    if (i < 2 * 128) g_stats[i] = 0.f;
}

// ---------------- graph preprocessing ----------------

__global__ void deg_count_k(const int* __restrict__ ei32) {
    int e = blockIdx.x * blockDim.x + threadIdx.x;
    if (e >= EE) return;
    int s, d;
    load_edge(ei32, e, s, d);
    if ((unsigned)s >= NN || (unsigned)d >= NN) return;
    if (s != d) { atomicAdd(&g_deg[s], 1); atomicAdd(&g_cnt[d], 1); }
}

__global__ void dinv_k() {
    int i = blockIdx.x * blockDim.x + threadIdx.x;
    if (i >= NN) return;
    int d = g_deg[i];
    g_dinv[i] = (d > 0) ? rsqrtf((float)d) : 0.0f;
}

__global__ void scan_block_k() {
    __shared__ int sh[1024];
    int i = blockIdx.x * 1024 + threadIdx.x;
    int v = (i < NN) ? g_cnt[i] : 0;
    sh[threadIdx.x] = v;
    __syncthreads();
    for (int off = 1; off < 1024; off <<= 1) {
        int t = (threadIdx.x >= off) ? sh[threadIdx.x - off] : 0;
        __syncthreads();
        sh[threadIdx.x] += t;
        __syncthreads();
    }
    if (i < NN) g_rowptr[i] = sh[threadIdx.x] - v;
    if (threadIdx.x == 1023) g_bsum[blockIdx.x] = sh[1023];
}

__global__ void scan_top_k(int nb) {
    if (threadIdx.x == 0) {
        int run = 0;
        for (int b = 0; b < nb; b++) { int t = g_bsum[b]; g_bsum[b] = run; run += t; }
        g_total[0] = run;
    }
}

__global__ void scan_add_k() {
    int i = blockIdx.x * blockDim.x + threadIdx.x;
    if (i < NN) {
        int v = g_rowptr[i] + g_bsum[i >> 10];
        g_rowptr[i] = v;
        g_fill[i] = v;
    }
    if (i == NN) g_rowptr[NN] = g_total[0];
}

__global__ void scatter_k(const int* __restrict__ ei32) {
    int e = blockIdx.x * blockDim.x + threadIdx.x;
    if (e >= EE) return;
    int s, d;
    load_edge(ei32, e, s, d);
    if ((unsigned)s >= NN || (unsigned)d >= NN) return;
    if (s == d) return;
    int pos = atomicAdd(&g_fill[d], 1);
    g_col[pos] = s;
    g_w[pos] = -g_dinv[s] * g_dinv[d];
}

// ---------------- conversions ----------------

__global__ void conv_x_k(const float* __restrict__ x) {   // x -> slice 0 fp16
    int i = blockIdx.x * blockDim.x + threadIdx.x;
    if (i < NN * 128) g_big[i] = __float2half(x[i]);
}

__global__ void conv_w_k(const float* __restrict__ W1, const float* __restrict__ W2) {
    int i = blockIdx.x * blockDim.x + threadIdx.x;
    if (i < 16 * 128 * 128) g_W1h[i] = __float2half(W1[i]);
    if (i < 128 * 512) {
        int f = i >> 9, j = i & 511;
        g_W2t[i] = __float2half(W2[(j >> 5) * 128 * 32 + f * 32 + (j & 31)]);
    }
}

// ---------------- layer-1 sparse propagation (width 128, warp per dst row) ------

__global__ void prop_first2_k(int x_slice, int y_f, int y_slice) {
    const __half* __restrict__ X = g_big + (size_t)x_slice * NN * 128;
    float* __restrict__ Yf = fbuf(y_f);
    __half* __restrict__ Yh = g_big + (size_t)y_slice * NN * 128;
    int wid = (blockIdx.x * blockDim.x + threadIdx.x) >> 5;
    int lane = threadIdx.x & 31;
    if (wid >= NN) return;
    int beg = g_rowptr[wid], end = g_rowptr[wid + 1];
    float ax = 0.f, ay = 0.f, az = 0.f, aw = 0.f;
#pragma unroll 4
    for (int e = beg; e < end; e++) {
        int s = g_col[e];
        float w = g_w[e];
        uint2 u = ((const uint2*)(X + (size_t)s * 128))[lane];
        float2 f0 = __half22float2(*(__half2*)&u.x);
        float2 f1 = __half22float2(*(__half2*)&u.y);
        ax = fmaf(w, f0.x, ax);
        ay = fmaf(w, f0.y, ay);
        az = fmaf(w, f1.x, az);
        aw = fmaf(w, f1.y, aw);
    }
    ((float4*)(Yf + (size_t)wid * 128))[lane] = make_float4(ax, ay, az, aw);
    uint2 o;
    *(__half2*)&o.x = __floats2half2_rn(ax, ay);
    *(__half2*)&o.y = __floats2half2_rn(az, aw);
    ((uint2*)(Yh + (size_t)wid * 128))[lane] = o;
}

__global__ void prop_rec2_k(const float* __restrict__ x0ext, int x0_f,
                            int x1_slice, int y_f, int y_slice) {
    const __half* __restrict__ X1 = g_big + (size_t)x1_slice * NN * 128;
    const float* __restrict__ X0 = (x0_f < 0) ? x0ext : fbuf(x0_f);
    float* __restrict__ Yf = fbuf(y_f);
    __half* __restrict__ Yh = g_big + (size_t)y_slice * NN * 128;
    int wid = (blockIdx.x * blockDim.x + threadIdx.x) >> 5;
    int lane = threadIdx.x & 31;
    if (wid >= NN) return;
    int beg = g_rowptr[wid], end = g_rowptr[wid + 1];
    float ax = 0.f, ay = 0.f, az = 0.f, aw = 0.f;
#pragma unroll 4
    for (int e = beg; e < end; e++) {
        int s = g_col[e];
        float w = g_w[e];
        uint2 u = ((const uint2*)(X1 + (size_t)s * 128))[lane];
        float2 f0 = __half22float2(*(__half2*)&u.x);
        float2 f1 = __half22float2(*(__half2*)&u.y);
        ax = fmaf(w, f0.x, ax);
        ay = fmaf(w, f0.y, ay);
        az = fmaf(w, f1.x, az);
        aw = fmaf(w, f1.y, aw);
    }
    float4 p = ((const float4*)(X0 + (size_t)wid * 128))[lane];
    float ox = 2.f * ax - p.x;
    float oy = 2.f * ay - p.y;
    float oz = 2.f * az - p.z;
    float ow = 2.f * aw - p.w;
    ((float4*)(Yf + (size_t)wid * 128))[lane] = make_float4(ox, oy, oz, ow);
    uint2 o;
    *(__half2*)&o.x = __floats2half2_rn(ox, oy);
    *(__half2*)&o.y = __floats2half2_rn(oz, ow);
    ((uint2*)(Yh + (size_t)wid * 128))[lane] = o;
}

// ---------------- layer-1 fused tensor-core GEMM (K = 2048) ----------------

__global__ void gemm_tc128_k(int n) {
    const int warp = threadIdx.x >> 5;
    const int row0 = blockIdx.x * 128 + warp * 16;
    __shared__ __align__(32) __half Bs[16 * 128];
    wmma::fragment<wmma::accumulator, 16, 16, 16, float> acc[8];
#pragma unroll
    for (int i = 0; i < 8; i++) wmma::fill_fragment(acc[i], 0.f);

    for (int kc = 0; kc < 128; kc++) {
        ((uint4*)Bs)[threadIdx.x] = ((const uint4*)(g_W1h + (size_t)kc * 16 * 128))[threadIdx.x];
        __syncthreads();
        if (row0 < n) {
            int slice = kc >> 3;
            int f0 = (kc & 7) * 16;
            const __half* Ag = g_big + (size_t)slice * NN * 128 + (size_t)row0 * 128 + f0;
            wmma::fragment<wmma::matrix_a, 16, 16, 16, __half, wmma::row_major> a;
            wmma::load_matrix_sync(a, Ag, 128);
#pragma unroll
            for (int nf = 0; nf < 8; nf++) {
                wmma::fragment<wmma::matrix_b, 16, 16, 16, __half, wmma::row_major> b;
                wmma::load_matrix_sync(b, Bs + nf * 16, 128);
                wmma::mma_sync(acc[nf], a, b, acc[nf]);
            }
        }
        __syncthreads();
    }
    if (row0 < n) {
#pragma unroll
        for (int nf = 0; nf < 8; nf++)
            wmma::store_matrix_sync(g_out1 + (size_t)row0 * 128 + nf * 16, acc[nf],
                                    128, wmma::mem_row_major);
    }
}

// ---------------- layer-2: P = h * W2 (all 16 taps), P[k][N][32] ----------------
// A = g_big slice 0 (fp16 h), B = W2t [128 x 512]. grid: (rows/128, 4 col-blocks)

__global__ void gemm_P_k(int n) {
    const int warp = threadIdx.x >> 5;
    const int row0 = blockIdx.x * 128 + warp * 16;
    const int jb = blockIdx.y;              // 128-col block: cols jb*128..+127
    __shared__ __align__(32) __half Bs[16 * 128];
    wmma::fragment<wmma::accumulator, 16, 16, 16, float> acc[8];
#pragma unroll
    for (int i = 0; i < 8; i++) wmma::fill_fragment(acc[i], 0.f);

    for (int kc = 0; kc < 8; kc++) {        // K = 128
        int t = threadIdx.x >> 4, u = threadIdx.x & 15;
        ((uint4*)Bs)[threadIdx.x] =
            *(const uint4*)(g_W2t + (size_t)(kc * 16 + t) * 512 + jb * 128 + u * 8);
        __syncthreads();
        if (row0 < n) {
            const __half* Ag = g_big + (size_t)row0 * 128 + kc * 16;
            wmma::fragment<wmma::matrix_a, 16, 16, 16, __half, wmma::row_major> a;
            wmma::load_matrix_sync(a, Ag, 128);
#pragma unroll
            for (int nf = 0; nf < 8; nf++) {
                wmma::fragment<wmma::matrix_b, 16, 16, 16, __half, wmma::row_major> b;
                wmma::load_matrix_sync(b, Bs + nf * 16, 128);
                wmma::mma_sync(acc[nf], a, b, acc[nf]);
            }
        }
        __syncthreads();
    }
    if (row0 < n) {
#pragma unroll
        for (int nf = 0; nf < 8; nf++) {
            int j0 = jb * 128 + nf * 16;     // global col; k = j0>>5, within-k col = j0&31
            wmma::store_matrix_sync(g_P + (size_t)(j0 >> 5) * NN * 32 +
                                        (size_t)row0 * 32 + (j0 & 31),
                                    acc[nf], 32, wmma::mem_row_major);
        }
    }
}

// B_15 = P_15 (copy into chain buffer b_idx, fp32 + fp16 mirror)
__global__ void p_copy_k(int b_idx) {
    int i = blockIdx.x * blockDim.x + threadIdx.x;
    if (i >= NN * 32) return;
    float v = g_P[(size_t)15 * NN * 32 + i];
    g_Bf[b_idx][i] = v;
    g_Bh[b_idx][i] = __float2half(v);
}

// Clenshaw step: Bout = 2*L*B1 - B2 + P_k   (width 32, warp per dst row)
__global__ void clen_step_k(int b1, int b2, int pk, int outb) {
    int wid = (blockIdx.x * blockDim.x + threadIdx.x) >> 5;
    int lane = threadIdx.x & 31;
    if (wid >= NN) return;
    const __half* __restrict__ B1h = g_Bh[b1];
    int beg = g_rowptr[wid], end = g_rowptr[wid + 1];
    float acc = 0.f;
#pragma unroll 4
    for (int e = beg; e < end; e++) {
        int s = g_col[e];
        float w = g_w[e];
        acc = fmaf(w, __half2float(B1h[(size_t)s * 32 + lane]), acc);
    }
    size_t idx = (size_t)wid * 32 + lane;
    float x0 = (b2 >= 0) ? g_Bf[b2][idx] : 0.f;
    float v = 2.f * acc - x0 + g_P[(size_t)pk * NN * 32 + idx];
    g_Bf[outb][idx] = v;
    g_Bh[outb][idx] = __float2half(v);
}

// Final: out2 = L*B1 - B2 + P_0
__global__ void clen_final_k(int b1, int b2) {
    int wid = (blockIdx.x * blockDim.x + threadIdx.x) >> 5;
    int lane = threadIdx.x & 31;
    if (wid >= NN) return;
    const __half* __restrict__ B1h = g_Bh[b1];
    int beg = g_rowptr[wid], end = g_rowptr[wid + 1];
    float acc = 0.f;
#pragma unroll 4
    for (int e = beg; e < end; e++) {
        int s = g_col[e];
        float w = g_w[e];
        acc = fmaf(w, __half2float(B1h[(size_t)s * 32 + lane]), acc);
    }
    size_t idx = (size_t)wid * 32 + lane;
    g_out2[idx] = acc - g_Bf[b2][idx] + g_P[idx];
}

// ---------------- BatchNorm (training-mode) + ReLU ----------------

__global__ void bn_stats_k(int v_f, int total, int F) {
    const float* __restrict__ V = fbuf(v_f);
    int idx = blockIdx.x * blockDim.x + threadIdx.x;
    int stride = gridDim.x * blockDim.x;
    float s = 0.f, s2 = 0.f;
    int col = idx % F;
    for (int i = idx; i < total; i += stride) {
        float v = V[i];
        s += v;
        s2 = fmaf(v, v, s2);
    }
    atomicAdd(&g_stats[col], s);
    atomicAdd(&g_stats[F + col], s2);
}

__global__ void bn_finalize_k(const float* __restrict__ gamma,
                              const float* __restrict__ beta, int F, float invN) {
    int c = threadIdx.x;
    if (c < F) {
        float mu = g_stats[c] * invN;
        float var = g_stats[F + c] * invN - mu * mu;
        float sc = gamma[c] * rsqrtf(var + BN_EPS);
        g_stats[c] = sc;
        g_stats[F + c] = beta[c] - sc * mu;
    }
}

// BN+ReLU; optionally write fp32 ext (write_ext) and/or fp16 into g_big slice.
__global__ void bn_apply_k(int v_f, float* __restrict__ Yext, int write_ext,
                           int yh_slice, int total, int F) {
    const float* __restrict__ V = fbuf(v_f);
    int idx = blockIdx.x * blockDim.x + threadIdx.x;
    if (idx >= total) return;
    int c = idx % F;
    float y = fmaf(g_stats[c], V[idx], g_stats[F + c]);
    y = fmaxf(y, 0.f);
    if (write_ext) Yext[idx] = y;
    if (yh_slice >= 0) g_big[(size_t)yh_slice * NN * 128 + idx] = __float2half(y);
}

// ---------------- host launch: kernel launches ONLY ----------------

extern "C" void kernel_launch(void* const* d_in, const int* in_sizes, int n_in,
                              void* d_out, int out_size) {
    const float* x  = (const float*)d_in[0];
    const int* ei32 = (const int*)d_in[1];
    const float* W1 = (const float*)d_in[2];
    const float* W2 = (const float*)d_in[4];
    const float* g1 = (const float*)d_in[6];
    const float* be1 = (const float*)d_in[7];
    const float* g2 = (const float*)d_in[8];
    const float* be2 = (const float*)d_in[9];
    float* out = (float*)d_out;

    // float buffers: 0=TxA 1=TxB 2=TxC 3=out1 4=out2 ; -1 = external
    const int FA = 0, FB = 1, FC = 2, FO1 = 3, FO2 = 4, EXT = -1;

    // --- preprocessing ---
    detect_init_k<<<1, 32>>>();
    detect_k<<<16, 256>>>(ei32);
    zero_graph_k<<<(NN + 255) / 256, 256>>>();
    deg_count_k<<<(EE + 255) / 256, 256>>>(ei32);
    dinv_k<<<(NN + 255) / 256, 256>>>();
    int nb = (NN + 1023) / 1024;
    scan_block_k<<<nb, 1024>>>();
    scan_top_k<<<1, 32>>>(nb);
    scan_add_k<<<(NN + 1 + 255) / 256, 256>>>();
    scatter_k<<<(EE + 255) / 256, 256>>>(ei32);
    conv_w_k<<<(16 * 128 * 128 + 255) / 256, 256>>>(W1, W2);

    const int PROP_GRID = (NN * 32 + 255) / 256;
    const int GT = (NN + 127) / 128;

    // --- layer 1: ChebConv(128 -> 128), direct recurrence + fused GEMM ---
    conv_x_k<<<(NN * 128 + 255) / 256, 256>>>(x);
    prop_first2_k<<<PROP_GRID, 256>>>(0, FA, 1);
    {
        int pp = EXT, p1 = FA;
        const int bufs[3] = {FA, FB, FC};
        int bi = 1;
        for (int k = 2; k < K_CHEB; k++) {
            int dst = bufs[bi];
            bi = (bi + 1) % 3;
            prop_rec2_k<<<PROP_GRID, 256>>>(x, pp, k - 1, dst, k);
            pp = p1;
            p1 = dst;
        }
    }
    gemm_tc128_k<<<GT, 256>>>(NN);
    zero_stats_k<<<1, 256>>>();
    bn_stats_k<<<256, 256>>>(FO1, NN * 128, 128);
    bn_finalize_k<<<1, 128>>>(g1, be1, 128, 1.0f / NN);
    bn_apply_k<<<(NN * 128 + 255) / 256, 256>>>(FO1, nullptr, 0, 0, NN * 128, 128);

    // --- layer 2: ChebConv(128 -> 32) via Clenshaw on width-32 operands ---
    {
        dim3 gp(GT, 4);
        gemm_P_k<<<gp, 256>>>(NN);              // P[k] = h * W2[k], all k
    }
    p_copy_k<<<PROP_GRID, 256>>>(0);            // B15 in chain buf 0
    clen_step_k<<<PROP_GRID, 256>>>(0, -1, 14, 1);   // B14 = 2L B15 + P14
    {
        int prev = 0, cur = 1, fre = 2;
        for (int k = 13; k >= 1; k--) {
            clen_step_k<<<PROP_GRID, 256>>>(cur, prev, k, fre);
            int t = prev; prev = cur; cur = fre; fre = t;
        }
        clen_final_k<<<PROP_GRID, 256>>>(cur, prev);   // out2 = L B1 - B2 + P0
    }
    zero_stats_k<<<1, 256>>>();
    bn_stats_k<<<256, 256>>>(FO2, NN * 32, 32);
    bn_finalize_k<<<1, 32>>>(g2, be2, 32, 1.0f / NN);
    bn_apply_k<<<(NN * 32 + 255) / 256, 256>>>(FO2, out, 1, -1, NN * 32, 32);
}

// round 8
// speedup vs baseline: 2.4195x; 1.1600x over previous
#include <cuda_runtime.h>
#include <cuda_fp16.h>
#include <mma.h>
using namespace nvcuda;

// Problem constants
#define NN 50000
#define EE 800000
#define K_CHEB 16
#define BN_EPS 1e-5f

// ---------------- scratch (device globals; no allocation allowed) ----------------
__device__ int   g_is64;
__device__ int   g_deg[NN];
__device__ float g_dinv[NN];
__device__ int   g_cnt[NN];
__device__ int   g_rowptr[NN + 1];
__device__ int   g_fill[NN];
__device__ int   g_col[EE];
__device__ float g_w[EE];
__device__ int   g_bsum[64];
__device__ int   g_total[1];

// Big fp16 buffer: all 16 Chebyshev terms for layer 1 (slice 0 becomes h after BN)
__device__ __half g_big[(size_t)K_CHEB * NN * 128];       // 204.8 MB
// fp16 weights
__device__ __half g_W1h[16 * 128 * 128];
__device__ __half g_W2t[128 * 512];                       // W2t[f][k*32+c] = W2[k][f][c]
// layer outputs
__device__ float g_out1[(size_t)NN * 128];
__device__ float g_out2[(size_t)NN * 32];
__device__ float g_stats[2 * 128];
// Layer-2 Clenshaw: P[k][N][32] fp32, B chain fp32 + fp16 gather mirrors
__device__ float  g_P[(size_t)16 * NN * 32];              // 102.4 MB
__device__ float  g_Bf[3][(size_t)NN * 32];
__device__ __half g_Bh[3][(size_t)NN * 32];

// float buffers: 0=out1 1=out2
__device__ __forceinline__ float* fbuf(int i) {
    return (i == 0) ? g_out1 : g_out2;
}

// ---------------- edge dtype detection ----------------

__global__ void detect_init_k() { if (threadIdx.x == 0) g_is64 = 1; }

__global__ void detect_k(const int* __restrict__ ei32) {
    int e = blockIdx.x * blockDim.x + threadIdx.x;
    if (e >= 4096) return;
    if (ei32[2 * e + 1] != 0) g_is64 = 0;
}

__device__ __forceinline__ void load_edge(const int* __restrict__ ei32, int e,
                                          int& s, int& d) {
    if (g_is64) { s = ei32[2 * e]; d = ei32[2 * (EE + e)]; }
    else        { s = ei32[e];     d = ei32[EE + e]; }
}

// ---------------- zero-init ----------------

__global__ void zero_graph_k() {
    int i = blockIdx.x * blockDim.x + threadIdx.x;
    if (i < NN) { g_deg[i] = 0; g_cnt[i] = 0; }
}

__global__ void zero_stats_k() {
    int i = threadIdx.x;
    if (i < 2 * 128) g_stats[i] = 0.f;
}

// ---------------- graph preprocessing ----------------

__global__ void deg_count_k(const int* __restrict__ ei32) {
    int e = blockIdx.x * blockDim.x + threadIdx.x;
    if (e >= EE) return;
    int s, d;
    load_edge(ei32, e, s, d);
    if ((unsigned)s >= NN || (unsigned)d >= NN) return;
    if (s != d) { atomicAdd(&g_deg[s], 1); atomicAdd(&g_cnt[d], 1); }
}

__global__ void dinv_k() {
    int i = blockIdx.x * blockDim.x + threadIdx.x;
    if (i >= NN) return;
    int d = g_deg[i];
    g_dinv[i] = (d > 0) ? rsqrtf((float)d) : 0.0f;
}

__global__ void scan_block_k() {
    __shared__ int sh[1024];
    int i = blockIdx.x * 1024 + threadIdx.x;
    int v = (i < NN) ? g_cnt[i] : 0;
    sh[threadIdx.x] = v;
    __syncthreads();
    for (int off = 1; off < 1024; off <<= 1) {
        int t = (threadIdx.x >= off) ? sh[threadIdx.x - off] : 0;
        __syncthreads();
        sh[threadIdx.x] += t;
        __syncthreads();
    }
    if (i < NN) g_rowptr[i] = sh[threadIdx.x] - v;
    if (threadIdx.x == 1023) g_bsum[blockIdx.x] = sh[1023];
}

__global__ void scan_top_k(int nb) {
    if (threadIdx.x == 0) {
        int run = 0;
        for (int b = 0; b < nb; b++) { int t = g_bsum[b]; g_bsum[b] = run; run += t; }
        g_total[0] = run;
    }
}

__global__ void scan_add_k() {
    int i = blockIdx.x * blockDim.x + threadIdx.x;
    if (i < NN) {
        int v = g_rowptr[i] + g_bsum[i >> 10];
        g_rowptr[i] = v;
        g_fill[i] = v;
    }
    if (i == NN) g_rowptr[NN] = g_total[0];
}

__global__ void scatter_k(const int* __restrict__ ei32) {
    int e = blockIdx.x * blockDim.x + threadIdx.x;
    if (e >= EE) return;
    int s, d;
    load_edge(ei32, e, s, d);
    if ((unsigned)s >= NN || (unsigned)d >= NN) return;
    if (s == d) return;
    int pos = atomicAdd(&g_fill[d], 1);
    g_col[pos] = s;
    g_w[pos] = -g_dinv[s] * g_dinv[d];
}

// ---------------- conversions ----------------

__global__ void conv_x_k(const float* __restrict__ x) {   // x -> slice 0 fp16
    int i = blockIdx.x * blockDim.x + threadIdx.x;
    if (i < NN * 128) g_big[i] = __float2half(x[i]);
}

__global__ void conv_w_k(const float* __restrict__ W1, const float* __restrict__ W2) {
    int i = blockIdx.x * blockDim.x + threadIdx.x;
    if (i < 16 * 128 * 128) g_W1h[i] = __float2half(W1[i]);
    if (i < 128 * 512) {
        int f = i >> 9, j = i & 511;
        g_W2t[i] = __float2half(W2[(j >> 5) * 128 * 32 + f * 32 + (j & 31)]);
    }
}

// ------- layer-1 propagation (width 128, warp per row, fp16 slices only) -------

__global__ void prop_first_s(int x_slice, int y_slice) {
    const __half* __restrict__ X = g_big + (size_t)x_slice * NN * 128;
    __half* __restrict__ Yh = g_big + (size_t)y_slice * NN * 128;
    int wid = (blockIdx.x * blockDim.x + threadIdx.x) >> 5;
    int lane = threadIdx.x & 31;
    if (wid >= NN) return;
    int beg = g_rowptr[wid], end = g_rowptr[wid + 1];
    float ax = 0.f, ay = 0.f, az = 0.f, aw = 0.f;
#pragma unroll 4
    for (int e = beg; e < end; e++) {
        int s = g_col[e];
        float w = g_w[e];
        uint2 u = ((const uint2*)(X + (size_t)s * 128))[lane];
        float2 f0 = __half22float2(*(__half2*)&u.x);
        float2 f1 = __half22float2(*(__half2*)&u.y);
        ax = fmaf(w, f0.x, ax);
        ay = fmaf(w, f0.y, ay);
        az = fmaf(w, f1.x, az);
        aw = fmaf(w, f1.y, aw);
    }
    uint2 o;
    *(__half2*)&o.x = __floats2half2_rn(ax, ay);
    *(__half2*)&o.y = __floats2half2_rn(az, aw);
    ((uint2*)(Yh + (size_t)wid * 128))[lane] = o;
}

// Tx_k = 2 L Tx_{k-1} - Tx_{k-2}; X1 = slice k-1, X0 = slice k-2, Y = slice k
__global__ void prop_rec_s(int x1_slice, int x0_slice, int y_slice) {
    const __half* __restrict__ X1 = g_big + (size_t)x1_slice * NN * 128;
    const __half* __restrict__ X0 = g_big + (size_t)x0_slice * NN * 128;
    __half* __restrict__ Yh = g_big + (size_t)y_slice * NN * 128;
    int wid = (blockIdx.x * blockDim.x + threadIdx.x) >> 5;
    int lane = threadIdx.x & 31;
    if (wid >= NN) return;
    int beg = g_rowptr[wid], end = g_rowptr[wid + 1];
    float ax = 0.f, ay = 0.f, az = 0.f, aw = 0.f;
#pragma unroll 4
    for (int e = beg; e < end; e++) {
        int s = g_col[e];
        float w = g_w[e];
        uint2 u = ((const uint2*)(X1 + (size_t)s * 128))[lane];
        float2 f0 = __half22float2(*(__half2*)&u.x);
        float2 f1 = __half22float2(*(__half2*)&u.y);
        ax = fmaf(w, f0.x, ax);
        ay = fmaf(w, f0.y, ay);
        az = fmaf(w, f1.x, az);
        aw = fmaf(w, f1.y, aw);
    }
    uint2 p = ((const uint2*)(X0 + (size_t)wid * 128))[lane];
    float2 p0 = __half22float2(*(__half2*)&p.x);
    float2 p1 = __half22float2(*(__half2*)&p.y);
    uint2 o;
    *(__half2*)&o.x = __floats2half2_rn(2.f * ax - p0.x, 2.f * ay - p0.y);
    *(__half2*)&o.y = __floats2half2_rn(2.f * az - p1.x, 2.f * aw - p1.y);
    ((uint2*)(Yh + (size_t)wid * 128))[lane] = o;
}

// ---------------- layer-1 fused tensor-core GEMM (K = 2048) ----------------

__global__ void gemm_tc128_k(int n) {
    const int warp = threadIdx.x >> 5;
    const int row0 = blockIdx.x * 128 + warp * 16;
    __shared__ __align__(32) __half Bs[16 * 128];
    wmma::fragment<wmma::accumulator, 16, 16, 16, float> acc[8];
#pragma unroll
    for (int i = 0; i < 8; i++) wmma::fill_fragment(acc[i], 0.f);

    for (int kc = 0; kc < 128; kc++) {
        ((uint4*)Bs)[threadIdx.x] = ((const uint4*)(g_W1h + (size_t)kc * 16 * 128))[threadIdx.x];
        __syncthreads();
        if (row0 < n) {
            int slice = kc >> 3;
            int f0 = (kc & 7) * 16;
            const __half* Ag = g_big + (size_t)slice * NN * 128 + (size_t)row0 * 128 + f0;
            wmma::fragment<wmma::matrix_a, 16, 16, 16, __half, wmma::row_major> a;
            wmma::load_matrix_sync(a, Ag, 128);
#pragma unroll
            for (int nf = 0; nf < 8; nf++) {
                wmma::fragment<wmma::matrix_b, 16, 16, 16, __half, wmma::row_major> b;
                wmma::load_matrix_sync(b, Bs + nf * 16, 128);
                wmma::mma_sync(acc[nf], a, b, acc[nf]);
            }
        }
        __syncthreads();
    }
    if (row0 < n) {
#pragma unroll
        for (int nf = 0; nf < 8; nf++)
            wmma::store_matrix_sync(g_out1 + (size_t)row0 * 128 + nf * 16, acc[nf],
                                    128, wmma::mem_row_major);
    }
}

// ---------------- layer-2: P = h * W2 (all 16 taps), P[k][N][32] ----------------

__global__ void gemm_P_k(int n) {
    const int warp = threadIdx.x >> 5;
    const int row0 = blockIdx.x * 128 + warp * 16;
    const int jb = blockIdx.y;              // 128-col block of the 512-wide output
    __shared__ __align__(32) __half Bs[16 * 128];
    wmma::fragment<wmma::accumulator, 16, 16, 16, float> acc[8];
#pragma unroll
    for (int i = 0; i < 8; i++) wmma::fill_fragment(acc[i], 0.f);

    for (int kc = 0; kc < 8; kc++) {        // K = 128
        int t = threadIdx.x >> 4, u = threadIdx.x & 15;
        ((uint4*)Bs)[threadIdx.x] =
            *(const uint4*)(g_W2t + (size_t)(kc * 16 + t) * 512 + jb * 128 + u * 8);
        __syncthreads();
        if (row0 < n) {
            const __half* Ag = g_big + (size_t)row0 * 128 + kc * 16;
            wmma::fragment<wmma::matrix_a, 16, 16, 16, __half, wmma::row_major> a;
            wmma::load_matrix_sync(a, Ag, 128);
#pragma unroll
            for (int nf = 0; nf < 8; nf++) {
                wmma::fragment<wmma::matrix_b, 16, 16, 16, __half, wmma::row_major> b;
                wmma::load_matrix_sync(b, Bs + nf * 16, 128);
                wmma::mma_sync(acc[nf], a, b, acc[nf]);
            }
        }
        __syncthreads();
    }
    if (row0 < n) {
#pragma unroll
        for (int nf = 0; nf < 8; nf++) {
            int j0 = jb * 128 + nf * 16;
            wmma::store_matrix_sync(g_P + (size_t)(j0 >> 5) * NN * 32 +
                                        (size_t)row0 * 32 + (j0 & 31),
                                    acc[nf], 32, wmma::mem_row_major);
        }
    }
}

// B_15 = P_15
__global__ void p_copy_k(int b_idx) {
    int i = blockIdx.x * blockDim.x + threadIdx.x;
    if (i >= NN * 32) return;
    float v = g_P[(size_t)15 * NN * 32 + i];
    g_Bf[b_idx][i] = v;
    g_Bh[b_idx][i] = __float2half(v);
}

// Clenshaw step, 4 rows per warp: 8 lanes per row, each lane owns 4 columns.
// Bout = 2*L*B1 - B2 + P_k
__global__ void clen_step_k(int b1, int b2, int pk, int outb) {
    int t = blockIdx.x * blockDim.x + threadIdx.x;
    int row = t >> 3;            // 8 threads per row
    int sl = t & 7;              // lane-in-row: columns sl*4 .. sl*4+3
    if (row >= NN) return;
    const __half* __restrict__ B1h = g_Bh[b1];
    int beg = g_rowptr[row], end = g_rowptr[row + 1];
    float a0 = 0.f, a1 = 0.f, a2 = 0.f, a3 = 0.f;
#pragma unroll 4
    for (int e = beg; e < end; e++) {
        int s = g_col[e];
        float w = g_w[e];
        uint2 u = ((const uint2*)(B1h + (size_t)s * 32))[sl];   // 4 halfs
        float2 f0 = __half22float2(*(__half2*)&u.x);
        float2 f1 = __half22float2(*(__half2*)&u.y);
        a0 = fmaf(w, f0.x, a0);
        a1 = fmaf(w, f0.y, a1);
        a2 = fmaf(w, f1.x, a2);
        a3 = fmaf(w, f1.y, a3);
    }
    size_t idx = (size_t)row * 32 + sl * 4;
    float4 x0 = (b2 >= 0) ? *(const float4*)&g_Bf[b2][idx]
                          : make_float4(0.f, 0.f, 0.f, 0.f);
    float4 pv = *(const float4*)&g_P[(size_t)pk * NN * 32 + idx];
    float4 v;
    v.x = 2.f * a0 - x0.x + pv.x;
    v.y = 2.f * a1 - x0.y + pv.y;
    v.z = 2.f * a2 - x0.z + pv.z;
    v.w = 2.f * a3 - x0.w + pv.w;
    *(float4*)&g_Bf[outb][idx] = v;
    uint2 o;
    *(__half2*)&o.x = __floats2half2_rn(v.x, v.y);
    *(__half2*)&o.y = __floats2half2_rn(v.z, v.w);
    *(uint2*)&g_Bh[outb][idx] = o;
}

// Final: out2 = L*B1 - B2 + P_0
__global__ void clen_final_k(int b1, int b2) {
    int t = blockIdx.x * blockDim.x + threadIdx.x;
    int row = t >> 3;
    int sl = t & 7;
    if (row >= NN) return;
    const __half* __restrict__ B1h = g_Bh[b1];
    int beg = g_rowptr[row], end = g_rowptr[row + 1];
    float a0 = 0.f, a1 = 0.f, a2 = 0.f, a3 = 0.f;
#pragma unroll 4
    for (int e = beg; e < end; e++) {
        int s = g_col[e];
        float w = g_w[e];
        uint2 u = ((const uint2*)(B1h + (size_t)s * 32))[sl];
        float2 f0 = __half22float2(*(__half2*)&u.x);
        float2 f1 = __half22float2(*(__half2*)&u.y);
        a0 = fmaf(w, f0.x, a0);
        a1 = fmaf(w, f0.y, a1);
        a2 = fmaf(w, f1.x, a2);
        a3 = fmaf(w, f1.y, a3);
    }
    size_t idx = (size_t)row * 32 + sl * 4;
    float4 x0 = *(const float4*)&g_Bf[b2][idx];
    float4 pv = *(const float4*)&g_P[idx];
    float4 v;
    v.x = a0 - x0.x + pv.x;
    v.y = a1 - x0.y + pv.y;
    v.z = a2 - x0.z + pv.z;
    v.w = a3 - x0.w + pv.w;
    *(float4*)&g_out2[idx] = v;
}

// ---------------- BatchNorm (training-mode) + ReLU ----------------

__global__ void bn_stats_k(int v_f, int total, int F) {
    const float* __restrict__ V = fbuf(v_f);
    int idx = blockIdx.x * blockDim.x + threadIdx.x;
    int stride = gridDim.x * blockDim.x;
    float s = 0.f, s2 = 0.f;
    int col = idx % F;
    for (int i = idx; i < total; i += stride) {
        float v = V[i];
        s += v;
        s2 = fmaf(v, v, s2);
    }
    atomicAdd(&g_stats[col], s);
    atomicAdd(&g_stats[F + col], s2);
}

__global__ void bn_finalize_k(const float* __restrict__ gamma,
                              const float* __restrict__ beta, int F, float invN) {
    int c = threadIdx.x;
    if (c < F) {
        float mu = g_stats[c] * invN;
        float var = g_stats[F + c] * invN - mu * mu;
        float sc = gamma[c] * rsqrtf(var + BN_EPS);
        g_stats[c] = sc;
        g_stats[F + c] = beta[c] - sc * mu;
    }
}

__global__ void bn_apply_k(int v_f, float* __restrict__ Yext, int write_ext,
                           int yh_slice, int total, int F) {
    const float* __restrict__ V = fbuf(v_f);
    int idx = blockIdx.x * blockDim.x + threadIdx.x;
    if (idx >= total) return;
    int c = idx % F;
    float y = fmaf(g_stats[c], V[idx], g_stats[F + c]);
    y = fmaxf(y, 0.f);
    if (write_ext) Yext[idx] = y;
    if (yh_slice >= 0) g_big[(size_t)yh_slice * NN * 128 + idx] = __float2half(y);
}

// ---------------- host launch: kernel launches ONLY ----------------

extern "C" void kernel_launch(void* const* d_in, const int* in_sizes, int n_in,
                              void* d_out, int out_size) {
    const float* x  = (const float*)d_in[0];
    const int* ei32 = (const int*)d_in[1];
    const float* W1 = (const float*)d_in[2];
    const float* W2 = (const float*)d_in[4];
    const float* g1 = (const float*)d_in[6];
    const float* be1 = (const float*)d_in[7];
    const float* g2 = (const float*)d_in[8];
    const float* be2 = (const float*)d_in[9];
    float* out = (float*)d_out;

    const int FO1 = 0, FO2 = 1;

    // --- preprocessing ---
    detect_init_k<<<1, 32>>>();
    detect_k<<<16, 256>>>(ei32);
    zero_graph_k<<<(NN + 255) / 256, 256>>>();
    deg_count_k<<<(EE + 255) / 256, 256>>>(ei32);
    dinv_k<<<(NN + 255) / 256, 256>>>();
    int nb = (NN + 1023) / 1024;
    scan_block_k<<<nb, 1024>>>();
    scan_top_k<<<1, 32>>>(nb);
    scan_add_k<<<(NN + 1 + 255) / 256, 256>>>();
    scatter_k<<<(EE + 255) / 256, 256>>>(ei32);
    conv_w_k<<<(16 * 128 * 128 + 255) / 256, 256>>>(W1, W2);

    const int PROP_GRID = (NN * 32 + 255) / 256;     // warp per row
    const int CLEN_GRID = (NN * 8 + 255) / 256;      // 8 threads per row
    const int GT = (NN + 127) / 128;

    // --- layer 1: ChebConv(128 -> 128), fp16 slice recurrence + fused GEMM ---
    conv_x_k<<<(NN * 128 + 255) / 256, 256>>>(x);
    prop_first_s<<<PROP_GRID, 256>>>(0, 1);
    for (int k = 2; k < K_CHEB; k++)
        prop_rec_s<<<PROP_GRID, 256>>>(k - 1, k - 2, k);
    gemm_tc128_k<<<GT, 256>>>(NN);
    zero_stats_k<<<1, 256>>>();
    bn_stats_k<<<256, 256>>>(FO1, NN * 128, 128);
    bn_finalize_k<<<1, 128>>>(g1, be1, 128, 1.0f / NN);
    bn_apply_k<<<(NN * 128 + 255) / 256, 256>>>(FO1, nullptr, 0, 0, NN * 128, 128);

    // --- layer 2: ChebConv(128 -> 32) via Clenshaw on width-32 operands ---
    {
        dim3 gp(GT, 4);
        gemm_P_k<<<gp, 256>>>(NN);              // P[k] = h * W2[k], all k
    }
    p_copy_k<<<(NN * 32 + 255) / 256, 256>>>(0);          // B15
    clen_step_k<<<CLEN_GRID, 256>>>(0, -1, 14, 1);        // B14 = 2L B15 + P14
    {
        int prev = 0, cur = 1, fre = 2;
        for (int k = 13; k >= 1; k--) {
            clen_step_k<<<CLEN_GRID, 256>>>(cur, prev, k, fre);
            int t = prev; prev = cur; cur = fre; fre = t;
        }
        clen_final_k<<<CLEN_GRID, 256>>>(cur, prev);      // out2 = L B1 - B2 + P0
    }
    zero_stats_k<<<1, 256>>>();
    bn_stats_k<<<256, 256>>>(FO2, NN * 32, 32);
    bn_finalize_k<<<1, 32>>>(g2, be2, 32, 1.0f / NN);
    bn_apply_k<<<(NN * 32 + 255) / 256, 256>>>(FO2, out, 1, -1, NN * 32, 32);
}